// round 2
// baseline (speedup 1.0000x reference)
#include <cuda_runtime.h>
#include <cstdint>
#include <cstddef>

// ---------------------------------------------------------------------------
// MolGIN: AtomEncoder -> 4x (GINConv: scatter-add + MLP(128->256->128) with
// training-mode BatchNorm + ReLU) -> global_add_pool -> projection 128->768.
// Baseline: fp32 SIMT GEMMs with fused BN-stat accumulation, red.v4 scatter.
// Index inputs are int32 (JAX silently downcasts int64 without x64 mode).
// ---------------------------------------------------------------------------

#define H      128
#define H2     256
#define NMAX   100000
#define GMAX   4096
#define DOUT   768

// Scratch (device globals: no allocation allowed in kernel_launch)
__device__ float g_h   [NMAX * H];    // node features
__device__ float g_z   [NMAX * H];    // aggregated input / reused as t2
__device__ float g_t1  [NMAX * H2];   // hidden (256) activations
__device__ float g_sum [H2];
__device__ float g_sq  [H2];
__device__ float g_scale[H2];
__device__ float g_shift[H2];
__device__ float g_pool[GMAX * H];

__device__ __constant__ int c_off[9] = {0, 119, 129, 140, 152, 161, 166, 174, 176};

__device__ __forceinline__ void red_add_v4(float* p, float4 v) {
    asm volatile("red.global.add.v4.f32 [%0], {%1,%2,%3,%4};"
                 :: "l"(p), "f"(v.x), "f"(v.y), "f"(v.z), "f"(v.w) : "memory");
}

// ---------------------------------------------------------------------------
// AtomEncoder: h[n] = sum_f emb[x[n][f] + off[f]]
// ---------------------------------------------------------------------------
__global__ void embed_kernel(const int* __restrict__ x,
                             const float* __restrict__ emb,
                             int N) {
    __shared__ int idx[9];
    int n = blockIdx.x;
    int t = threadIdx.x;
    if (t < 9) idx[t] = x[(size_t)n * 9 + t] + c_off[t];
    __syncthreads();
    float s = 0.f;
#pragma unroll
    for (int f = 0; f < 9; ++f) s += emb[(size_t)idx[f] * H + t];
    g_h[(size_t)n * H + t] = s;
}

// z = (1 + eps[l]) * h
__global__ void init_z_kernel(int N, const float* __restrict__ eps, int l) {
    int i = blockIdx.x * blockDim.x + threadIdx.x;
    if (i >= N * (H / 4)) return;
    float s = 1.f + eps[l];
    float4 v = ((const float4*)g_h)[i];
    v.x *= s; v.y *= s; v.z *= s; v.w *= s;
    ((float4*)g_z)[i] = v;
}

// z[dst] += h[src]  (one warp per edge, float4 vector reductions)
__global__ void scatter_kernel(const int* __restrict__ ei, int E) {
    long long gid = (long long)blockIdx.x * blockDim.x + threadIdx.x;
    int e = (int)(gid >> 5);
    if (e >= E) return;
    int lane = (int)(gid & 31);
    int src = ei[e];
    int dst = ei[(size_t)E + e];
    float4 v = *(const float4*)(g_h + (size_t)src * H + lane * 4);
    red_add_v4(g_z + (size_t)dst * H + lane * 4, v);
}

__global__ void zero_stats_kernel() {
    int i = blockIdx.x * blockDim.x + threadIdx.x;
    if (i < H2) { g_sum[i] = 0.f; g_sq[i] = 0.f; }
}

__global__ void zero_pool_kernel(int G) {
    int i = blockIdx.x * blockDim.x + threadIdx.x;
    if (i < G * H) g_pool[i] = 0.f;
}

// ---------------------------------------------------------------------------
// C[N,NCOLS] = f(A)[N,K] @ W[K,NCOLS] + bias, f = relu(scale*x+shift) if FUSE_IN.
// Optionally accumulates per-column sum / sumsq of C (valid rows only).
// 128x128 tile, BK=8, 256 threads, 8x8 per thread.
// ---------------------------------------------------------------------------
template <int K, bool FUSE_IN, bool STATS>
__global__ void gemm_kernel(const float* __restrict__ A,
                            const float* __restrict__ W,
                            const float* __restrict__ bias,
                            float* __restrict__ C,
                            int N, int NCOLS) {
    __shared__ float As[8][128];
    __shared__ float Ws[8][128];
    __shared__ float sSum[128];
    __shared__ float sSq[128];

    int tid = threadIdx.x;
    int tx = tid & 15;        // column group
    int ty = tid >> 4;        // row group
    int rowBase = blockIdx.y * 128;
    int colBase = blockIdx.x * 128;

    int la_row = tid >> 1;
    int la_k   = (tid & 1) * 4;
    int lw_k   = tid >> 5;
    int lw_col = (tid & 31) * 4;

    float acc[8][8];
#pragma unroll
    for (int i = 0; i < 8; ++i)
#pragma unroll
        for (int j = 0; j < 8; ++j) acc[i][j] = 0.f;

    for (int k0 = 0; k0 < K; k0 += 8) {
        // A tile (transposed into smem)
        float4 av = make_float4(0.f, 0.f, 0.f, 0.f);
        int m = rowBase + la_row;
        if (m < N)
            av = *(const float4*)(A + (size_t)m * K + k0 + la_k);
        if (FUSE_IN) {
            int kk = k0 + la_k;
            av.x = fmaxf(av.x * g_scale[kk + 0] + g_shift[kk + 0], 0.f);
            av.y = fmaxf(av.y * g_scale[kk + 1] + g_shift[kk + 1], 0.f);
            av.z = fmaxf(av.z * g_scale[kk + 2] + g_shift[kk + 2], 0.f);
            av.w = fmaxf(av.w * g_scale[kk + 3] + g_shift[kk + 3], 0.f);
        }
        As[la_k + 0][la_row] = av.x;
        As[la_k + 1][la_row] = av.y;
        As[la_k + 2][la_row] = av.z;
        As[la_k + 3][la_row] = av.w;
        // W tile
        *(float4*)&Ws[lw_k][lw_col] =
            *(const float4*)(W + (size_t)(k0 + lw_k) * NCOLS + colBase + lw_col);
        __syncthreads();
#pragma unroll
        for (int k = 0; k < 8; ++k) {
            float a[8], b[8];
            *(float4*)&a[0] = *(float4*)&As[k][ty * 8];
            *(float4*)&a[4] = *(float4*)&As[k][ty * 8 + 4];
            *(float4*)&b[0] = *(float4*)&Ws[k][tx * 8];
            *(float4*)&b[4] = *(float4*)&Ws[k][tx * 8 + 4];
#pragma unroll
            for (int i = 0; i < 8; ++i)
#pragma unroll
                for (int j = 0; j < 8; ++j) acc[i][j] += a[i] * b[j];
        }
        __syncthreads();
    }

    float bc[8];
#pragma unroll
    for (int j = 0; j < 8; ++j) bc[j] = bias[colBase + tx * 8 + j];

    if (STATS) {
        if (tid < 128) { sSum[tid] = 0.f; sSq[tid] = 0.f; }
        __syncthreads();
    }

    float ps[8], pq[8];
#pragma unroll
    for (int j = 0; j < 8; ++j) { ps[j] = 0.f; pq[j] = 0.f; }

#pragma unroll
    for (int i = 0; i < 8; ++i) {
        int m = rowBase + ty * 8 + i;
        if (m < N) {
            float4 lo, hi;
            float v;
            v = acc[i][0] + bc[0]; lo.x = v; if (STATS) { ps[0] += v; pq[0] += v * v; }
            v = acc[i][1] + bc[1]; lo.y = v; if (STATS) { ps[1] += v; pq[1] += v * v; }
            v = acc[i][2] + bc[2]; lo.z = v; if (STATS) { ps[2] += v; pq[2] += v * v; }
            v = acc[i][3] + bc[3]; lo.w = v; if (STATS) { ps[3] += v; pq[3] += v * v; }
            v = acc[i][4] + bc[4]; hi.x = v; if (STATS) { ps[4] += v; pq[4] += v * v; }
            v = acc[i][5] + bc[5]; hi.y = v; if (STATS) { ps[5] += v; pq[5] += v * v; }
            v = acc[i][6] + bc[6]; hi.z = v; if (STATS) { ps[6] += v; pq[6] += v * v; }
            v = acc[i][7] + bc[7]; hi.w = v; if (STATS) { ps[7] += v; pq[7] += v * v; }
            float* cp = C + (size_t)m * NCOLS + colBase + tx * 8;
            *(float4*)cp = lo;
            *(float4*)(cp + 4) = hi;
        }
    }

    if (STATS) {
#pragma unroll
        for (int j = 0; j < 8; ++j) {
            atomicAdd(&sSum[tx * 8 + j], ps[j]);
            atomicAdd(&sSq[tx * 8 + j], pq[j]);
        }
        __syncthreads();
        if (tid < 128) {
            atomicAdd(&g_sum[colBase + tid], sSum[tid]);
            atomicAdd(&g_sq[colBase + tid], sSq[tid]);
        }
    }
}

// scale/shift from accumulated stats (biased variance, eps=1e-5)
__global__ void finalize_bn_kernel(const float* __restrict__ gamma,
                                   const float* __restrict__ beta,
                                   int C, float invN) {
    int c = blockIdx.x * blockDim.x + threadIdx.x;
    if (c >= C) return;
    float m = g_sum[c] * invN;
    float v = g_sq[c] * invN - m * m;
    float s = gamma[c] * rsqrtf(v + 1e-5f);
    g_scale[c] = s;
    g_shift[c] = beta[c] - m * s;
}

// h = relu(scale * t2 + shift)   (t2 lives in g_z)
__global__ void bnrelu_kernel(int N) {
    int i = blockIdx.x * blockDim.x + threadIdx.x;
    if (i >= N * (H / 4)) return;
    int c = (i & 31) * 4;
    float4 v = ((const float4*)g_z)[i];
    v.x = fmaxf(v.x * g_scale[c + 0] + g_shift[c + 0], 0.f);
    v.y = fmaxf(v.y * g_scale[c + 1] + g_shift[c + 1], 0.f);
    v.z = fmaxf(v.z * g_scale[c + 2] + g_shift[c + 2], 0.f);
    v.w = fmaxf(v.w * g_scale[c + 3] + g_shift[c + 3], 0.f);
    ((float4*)g_h)[i] = v;
}

// g_pool[batch[n]] += relu(scale * t2[n] + shift)
__global__ void pool_kernel(const int* __restrict__ batch, int N) {
    long long gid = (long long)blockIdx.x * blockDim.x + threadIdx.x;
    int n = (int)(gid >> 5);
    if (n >= N) return;
    int lane = (int)(gid & 31);
    int c = lane * 4;
    int g = batch[n];
    float4 v = *(const float4*)(g_z + (size_t)n * H + c);
    v.x = fmaxf(v.x * g_scale[c + 0] + g_shift[c + 0], 0.f);
    v.y = fmaxf(v.y * g_scale[c + 1] + g_shift[c + 1], 0.f);
    v.z = fmaxf(v.z * g_scale[c + 2] + g_shift[c + 2], 0.f);
    v.w = fmaxf(v.w * g_scale[c + 3] + g_shift[c + 3], 0.f);
    red_add_v4(g_pool + (size_t)g * H + c, v);
}

static inline int cdiv(long long a, long long b) { return (int)((a + b - 1) / b); }

extern "C" void kernel_launch(void* const* d_in, const int* in_sizes, int n_in,
                              void* d_out, int out_size) {
    const int* x     = (const int*)d_in[0];
    const int* ei    = (const int*)d_in[1];
    const int* batch = (const int*)d_in[2];

    // Locate the float-parameter block by the embedding table's unique size
    // (178 * 128 = 22784). A size-1 num_graphs scalar may sit before it.
    int ib = 3;
    for (int i = 3; i < n_in; ++i)
        if (in_sizes[i] == 178 * H) { ib = i; break; }

    const float* emb   = (const float*)d_in[ib + 0];
    const float* W1    = (const float*)d_in[ib + 1];
    const float* b1    = (const float*)d_in[ib + 2];
    const float* g1    = (const float*)d_in[ib + 3];
    const float* be1   = (const float*)d_in[ib + 4];
    const float* W2    = (const float*)d_in[ib + 5];
    const float* b2    = (const float*)d_in[ib + 6];
    const float* g2    = (const float*)d_in[ib + 7];
    const float* be2   = (const float*)d_in[ib + 8];
    const float* eps   = (const float*)d_in[ib + 9];
    const float* projW = (const float*)d_in[ib + 10];
    const float* projb = (const float*)d_in[ib + 11];

    int N = in_sizes[0] / 9;
    int E = in_sizes[1] / 2;
    int G = out_size / DOUT;
    int L = in_sizes[ib + 9];  // eps has L entries

    float *p_z, *p_t1;
    cudaGetSymbolAddress((void**)&p_z, g_z);
    cudaGetSymbolAddress((void**)&p_t1, g_t1);

    float invN = 1.f / (float)N;

    embed_kernel<<<N, H>>>(x, emb, N);
    zero_pool_kernel<<<cdiv((long long)G * H, 256), 256>>>(G);

    for (int l = 0; l < L; ++l) {
        init_z_kernel<<<cdiv((long long)N * 32, 256), 256>>>(N, eps, l);
        scatter_kernel<<<cdiv((long long)E * 32, 256), 256>>>(ei, E);

        zero_stats_kernel<<<1, 256>>>();
        gemm_kernel<H, false, true><<<dim3(H2 / 128, cdiv(N, 128)), 256>>>(
            p_z, W1 + (size_t)l * H * H2, b1 + (size_t)l * H2, p_t1, N, H2);
        finalize_bn_kernel<<<1, 256>>>(g1 + (size_t)l * H2, be1 + (size_t)l * H2, H2, invN);

        zero_stats_kernel<<<1, 256>>>();
        gemm_kernel<H2, true, true><<<dim3(H / 128, cdiv(N, 128)), 256>>>(
            p_t1, W2 + (size_t)l * H2 * H, b2 + (size_t)l * H, p_z, N, H);
        finalize_bn_kernel<<<1, 128>>>(g2 + (size_t)l * H, be2 + (size_t)l * H, H, invN);

        if (l < L - 1)
            bnrelu_kernel<<<cdiv((long long)N * 32, 256), 256>>>(N);
    }

    pool_kernel<<<cdiv((long long)N * 32, 256), 256>>>(batch, N);

    float* p_pool;
    cudaGetSymbolAddress((void**)&p_pool, g_pool);
    gemm_kernel<H, false, false><<<dim3(DOUT / 128, cdiv(G, 128)), 256>>>(
        p_pool, projW, projb, (float*)d_out, G, DOUT);
}

// round 5
// speedup vs baseline: 1.0859x; 1.0859x over previous
#include <cuda_runtime.h>
#include <cstdint>
#include <cstddef>

// ---------------------------------------------------------------------------
// MolGIN: AtomEncoder -> 4x (GINConv: scatter-add + MLP(128->256->128) with
// training-mode BatchNorm + ReLU) -> global_add_pool -> projection 128->768.
// R5: 3xTF32 tensor-core GEMMs (hi/lo split, 3 MMAs) for fp32-grade accuracy.
// ---------------------------------------------------------------------------

#define H      128
#define H2     256
#define NMAX   100000
#define GMAX   4096
#define DOUT   768

__device__ float g_h   [NMAX * H];
__device__ float g_z   [NMAX * H];
__device__ float g_t1  [NMAX * H2];
__device__ float g_sum [H2];
__device__ float g_sq  [H2];
__device__ float g_scale[H2];
__device__ float g_shift[H2];
__device__ float g_pool[GMAX * H];

__device__ __constant__ int c_off[9] = {0, 119, 129, 140, 152, 161, 166, 174, 176};

// dynamic smem layout (floats):
//   As_hi[128][36] | As_lo[128][36] | Ws_hi[32][132] | Ws_lo[32][132] | sSum[128] | sSq[128]
#define AS_ELEMS (128 * 36)
#define WS_ELEMS (32 * 132)
#define SMEM_FLOATS (2 * AS_ELEMS + 2 * WS_ELEMS + 256)
#define SMEM_BYTES  (SMEM_FLOATS * 4)

__device__ __forceinline__ void red_add_v4(float* p, float4 v) {
    asm volatile("red.global.add.v4.f32 [%0], {%1,%2,%3,%4};"
                 :: "l"(p), "f"(v.x), "f"(v.y), "f"(v.z), "f"(v.w) : "memory");
}

__device__ __forceinline__ float to_tf32(float x) {
    uint32_t r;
    asm("cvt.rna.tf32.f32 %0, %1;" : "=r"(r) : "f"(x));
    return __uint_as_float(r);
}

__device__ __forceinline__ void mma_tf32(float& d0, float& d1, float& d2, float& d3,
                                         float a0, float a1, float a2, float a3,
                                         float b0, float b1) {
    asm("mma.sync.aligned.m16n8k8.row.col.f32.tf32.tf32.f32 "
        "{%0,%1,%2,%3}, {%4,%5,%6,%7}, {%8,%9}, {%0,%1,%2,%3};"
        : "+f"(d0), "+f"(d1), "+f"(d2), "+f"(d3)
        : "r"(__float_as_uint(a0)), "r"(__float_as_uint(a1)),
          "r"(__float_as_uint(a2)), "r"(__float_as_uint(a3)),
          "r"(__float_as_uint(b0)), "r"(__float_as_uint(b1)));
}

// ---------------------------------------------------------------------------
__global__ void embed_kernel(const int* __restrict__ x,
                             const float* __restrict__ emb, int N) {
    __shared__ int idx[9];
    int n = blockIdx.x;
    int t = threadIdx.x;
    if (t < 9) idx[t] = x[(size_t)n * 9 + t] + c_off[t];
    __syncthreads();
    float s = 0.f;
#pragma unroll
    for (int f = 0; f < 9; ++f) s += emb[(size_t)idx[f] * H + t];
    g_h[(size_t)n * H + t] = s;
}

__global__ void init_z_kernel(int N, const float* __restrict__ eps, int l) {
    int i = blockIdx.x * blockDim.x + threadIdx.x;
    if (i >= N * (H / 4)) return;
    float s = 1.f + eps[l];
    float4 v = ((const float4*)g_h)[i];
    v.x *= s; v.y *= s; v.z *= s; v.w *= s;
    ((float4*)g_z)[i] = v;
}

__global__ void scatter_kernel(const int* __restrict__ ei, int E) {
    long long gid = (long long)blockIdx.x * blockDim.x + threadIdx.x;
    int e = (int)(gid >> 5);
    if (e >= E) return;
    int lane = (int)(gid & 31);
    int src = ei[e];
    int dst = ei[(size_t)E + e];
    float4 v = *(const float4*)(g_h + (size_t)src * H + lane * 4);
    red_add_v4(g_z + (size_t)dst * H + lane * 4, v);
}

__global__ void zero_stats_kernel() {
    int i = blockIdx.x * blockDim.x + threadIdx.x;
    if (i < H2) { g_sum[i] = 0.f; g_sq[i] = 0.f; }
}

__global__ void zero_pool_kernel(int G) {
    int i = blockIdx.x * blockDim.x + threadIdx.x;
    if (i < G * H) g_pool[i] = 0.f;
}

// ---------------------------------------------------------------------------
// 3xTF32 tensor-core GEMM: C[N,NCOLS] = f(A)[N,K] @ W[K,NCOLS] + bias.
// f = relu(scale*x+shift) if FUSE_IN. Optional per-column sum/sumsq stats.
// 128x128 tile, BK=32, 8 warps (4Mx2N), warp tile 32x64, m16n8k8.
// ---------------------------------------------------------------------------
template <int K, bool FUSE_IN, bool STATS>
__global__ void __launch_bounds__(256)
gemm_tc(const float* __restrict__ A, const float* __restrict__ W,
        const float* __restrict__ bias, float* __restrict__ C,
        int N, int NCOLS) {
    extern __shared__ float smem[];
    float (*As_hi)[36]  = (float(*)[36])(smem);
    float (*As_lo)[36]  = (float(*)[36])(smem + AS_ELEMS);
    float (*Ws_hi)[132] = (float(*)[132])(smem + 2 * AS_ELEMS);
    float (*Ws_lo)[132] = (float(*)[132])(smem + 2 * AS_ELEMS + WS_ELEMS);
    float* sSum = smem + 2 * AS_ELEMS + 2 * WS_ELEMS;
    float* sSq  = sSum + 128;

    int tid  = threadIdx.x;
    int lane = tid & 31;
    int warp = tid >> 5;
    int q = lane >> 2;
    int c = lane & 3;
    int wm0 = (warp >> 1) * 32;
    int wn0 = (warp & 1) * 64;
    int rowBase = blockIdx.y * 128;
    int colBase = blockIdx.x * 128;

    if (STATS && tid < 128) { sSum[tid] = 0.f; sSq[tid] = 0.f; }

    float acc[2][8][4];
#pragma unroll
    for (int mt = 0; mt < 2; ++mt)
#pragma unroll
        for (int nt = 0; nt < 8; ++nt)
#pragma unroll
            for (int r = 0; r < 4; ++r) acc[mt][nt][r] = 0.f;

    int am  = tid >> 3;
    int akq = (tid & 7) * 4;
    int wkr = tid >> 5;
    int wn4 = (tid & 31) * 4;

    for (int k0 = 0; k0 < K; k0 += 32) {
        // ---- A tile: 128 x 32, hi/lo split ----
#pragma unroll
        for (int i = 0; i < 4; ++i) {
            int m  = am + i * 32;
            int gm = rowBase + m;
            float4 av = make_float4(0.f, 0.f, 0.f, 0.f);
            if (gm < N)
                av = *(const float4*)(A + (size_t)gm * K + k0 + akq);
            if (FUSE_IN) {
                int kk = k0 + akq;
                av.x = fmaxf(av.x * g_scale[kk + 0] + g_shift[kk + 0], 0.f);
                av.y = fmaxf(av.y * g_scale[kk + 1] + g_shift[kk + 1], 0.f);
                av.z = fmaxf(av.z * g_scale[kk + 2] + g_shift[kk + 2], 0.f);
                av.w = fmaxf(av.w * g_scale[kk + 3] + g_shift[kk + 3], 0.f);
            }
            float4 ah, al;
            ah.x = to_tf32(av.x); al.x = to_tf32(av.x - ah.x);
            ah.y = to_tf32(av.y); al.y = to_tf32(av.y - ah.y);
            ah.z = to_tf32(av.z); al.z = to_tf32(av.z - ah.z);
            ah.w = to_tf32(av.w); al.w = to_tf32(av.w - ah.w);
            *(float4*)&As_hi[m][akq] = ah;
            *(float4*)&As_lo[m][akq] = al;
        }
        // ---- W tile: 32 x 128, hi/lo split ----
#pragma unroll
        for (int i = 0; i < 4; ++i) {
            int k = wkr + i * 8;
            float4 wv = *(const float4*)(W + (size_t)(k0 + k) * NCOLS + colBase + wn4);
            float4 wh, wl;
            wh.x = to_tf32(wv.x); wl.x = to_tf32(wv.x - wh.x);
            wh.y = to_tf32(wv.y); wl.y = to_tf32(wv.y - wh.y);
            wh.z = to_tf32(wv.z); wl.z = to_tf32(wv.z - wh.z);
            wh.w = to_tf32(wv.w); wl.w = to_tf32(wv.w - wh.w);
            *(float4*)&Ws_hi[k][wn4] = wh;
            *(float4*)&Ws_lo[k][wn4] = wl;
        }
        __syncthreads();

#pragma unroll
        for (int kk = 0; kk < 32; kk += 8) {
            float ah[2][4], al[2][4];
#pragma unroll
            for (int mt = 0; mt < 2; ++mt) {
                int r0 = wm0 + mt * 16 + q;
                ah[mt][0] = As_hi[r0    ][kk + c];
                ah[mt][1] = As_hi[r0 + 8][kk + c];
                ah[mt][2] = As_hi[r0    ][kk + c + 4];
                ah[mt][3] = As_hi[r0 + 8][kk + c + 4];
                al[mt][0] = As_lo[r0    ][kk + c];
                al[mt][1] = As_lo[r0 + 8][kk + c];
                al[mt][2] = As_lo[r0    ][kk + c + 4];
                al[mt][3] = As_lo[r0 + 8][kk + c + 4];
            }
#pragma unroll
            for (int nt = 0; nt < 8; ++nt) {
                int n0 = wn0 + nt * 8 + q;
                float bh0 = Ws_hi[kk + c    ][n0];
                float bh1 = Ws_hi[kk + c + 4][n0];
                float bl0 = Ws_lo[kk + c    ][n0];
                float bl1 = Ws_lo[kk + c + 4][n0];
#pragma unroll
                for (int mt = 0; mt < 2; ++mt) {
                    // lo-first accumulation keeps small terms from being absorbed late
                    mma_tf32(acc[mt][nt][0], acc[mt][nt][1], acc[mt][nt][2], acc[mt][nt][3],
                             al[mt][0], al[mt][1], al[mt][2], al[mt][3], bh0, bh1);
                    mma_tf32(acc[mt][nt][0], acc[mt][nt][1], acc[mt][nt][2], acc[mt][nt][3],
                             ah[mt][0], ah[mt][1], ah[mt][2], ah[mt][3], bl0, bl1);
                    mma_tf32(acc[mt][nt][0], acc[mt][nt][1], acc[mt][nt][2], acc[mt][nt][3],
                             ah[mt][0], ah[mt][1], ah[mt][2], ah[mt][3], bh0, bh1);
                }
            }
        }
        __syncthreads();
    }

    // ---- epilogue ----
    float bc[8][2];
#pragma unroll
    for (int nt = 0; nt < 8; ++nt) {
        int col = colBase + wn0 + nt * 8 + 2 * c;
        bc[nt][0] = bias[col];
        bc[nt][1] = bias[col + 1];
    }

    float ps[8][2], pq[8][2];
    if (STATS) {
#pragma unroll
        for (int nt = 0; nt < 8; ++nt)
#pragma unroll
            for (int p = 0; p < 2; ++p) { ps[nt][p] = 0.f; pq[nt][p] = 0.f; }
    }

#pragma unroll
    for (int mt = 0; mt < 2; ++mt) {
        int r0 = rowBase + wm0 + mt * 16 + q;
        int r1 = r0 + 8;
        bool v0r = r0 < N, v1r = r1 < N;
#pragma unroll
        for (int nt = 0; nt < 8; ++nt) {
            int col = colBase + wn0 + nt * 8 + 2 * c;
            float v0 = acc[mt][nt][0] + bc[nt][0];
            float v1 = acc[mt][nt][1] + bc[nt][1];
            float v2 = acc[mt][nt][2] + bc[nt][0];
            float v3 = acc[mt][nt][3] + bc[nt][1];
            if (v0r) {
                *(float2*)(C + (size_t)r0 * NCOLS + col) = make_float2(v0, v1);
                if (STATS) {
                    ps[nt][0] += v0; pq[nt][0] += v0 * v0;
                    ps[nt][1] += v1; pq[nt][1] += v1 * v1;
                }
            }
            if (v1r) {
                *(float2*)(C + (size_t)r1 * NCOLS + col) = make_float2(v2, v3);
                if (STATS) {
                    ps[nt][0] += v2; pq[nt][0] += v2 * v2;
                    ps[nt][1] += v3; pq[nt][1] += v3 * v3;
                }
            }
        }
    }

    if (STATS) {
#pragma unroll
        for (int nt = 0; nt < 8; ++nt)
#pragma unroll
            for (int p = 0; p < 2; ++p) {
                float s = ps[nt][p], sq = pq[nt][p];
#pragma unroll
                for (int m = 4; m < 32; m <<= 1) {
                    s  += __shfl_xor_sync(0xffffffffu, s,  m);
                    sq += __shfl_xor_sync(0xffffffffu, sq, m);
                }
                if (lane < 4) {
                    atomicAdd(&sSum[wn0 + nt * 8 + 2 * c + p], s);
                    atomicAdd(&sSq [wn0 + nt * 8 + 2 * c + p], sq);
                }
            }
        __syncthreads();
        if (tid < 128) {
            atomicAdd(&g_sum[colBase + tid], sSum[tid]);
            atomicAdd(&g_sq [colBase + tid], sSq [tid]);
        }
    }
}

__global__ void finalize_bn_kernel(const float* __restrict__ gamma,
                                   const float* __restrict__ beta,
                                   int C, float invN) {
    int c = blockIdx.x * blockDim.x + threadIdx.x;
    if (c >= C) return;
    float m = g_sum[c] * invN;
    float v = g_sq[c] * invN - m * m;
    float s = gamma[c] * rsqrtf(v + 1e-5f);
    g_scale[c] = s;
    g_shift[c] = beta[c] - m * s;
}

__global__ void bnrelu_kernel(int N) {
    int i = blockIdx.x * blockDim.x + threadIdx.x;
    if (i >= N * (H / 4)) return;
    int c = (i & 31) * 4;
    float4 v = ((const float4*)g_z)[i];
    v.x = fmaxf(v.x * g_scale[c + 0] + g_shift[c + 0], 0.f);
    v.y = fmaxf(v.y * g_scale[c + 1] + g_shift[c + 1], 0.f);
    v.z = fmaxf(v.z * g_scale[c + 2] + g_shift[c + 2], 0.f);
    v.w = fmaxf(v.w * g_scale[c + 3] + g_shift[c + 3], 0.f);
    ((float4*)g_h)[i] = v;
}

__global__ void pool_kernel(const int* __restrict__ batch, int N) {
    long long gid = (long long)blockIdx.x * blockDim.x + threadIdx.x;
    int n = (int)(gid >> 5);
    if (n >= N) return;
    int lane = (int)(gid & 31);
    int c = lane * 4;
    int g = batch[n];
    float4 v = *(const float4*)(g_z + (size_t)n * H + c);
    v.x = fmaxf(v.x * g_scale[c + 0] + g_shift[c + 0], 0.f);
    v.y = fmaxf(v.y * g_scale[c + 1] + g_shift[c + 1], 0.f);
    v.z = fmaxf(v.z * g_scale[c + 2] + g_shift[c + 2], 0.f);
    v.w = fmaxf(v.w * g_scale[c + 3] + g_shift[c + 3], 0.f);
    red_add_v4(g_pool + (size_t)g * H + c, v);
}

static inline int cdiv(long long a, long long b) { return (int)((a + b - 1) / b); }

extern "C" void kernel_launch(void* const* d_in, const int* in_sizes, int n_in,
                              void* d_out, int out_size) {
    const int* x     = (const int*)d_in[0];
    const int* ei    = (const int*)d_in[1];
    const int* batch = (const int*)d_in[2];

    int ib = 3;
    for (int i = 3; i < n_in; ++i)
        if (in_sizes[i] == 178 * H) { ib = i; break; }

    const float* emb   = (const float*)d_in[ib + 0];
    const float* W1    = (const float*)d_in[ib + 1];
    const float* b1    = (const float*)d_in[ib + 2];
    const float* g1    = (const float*)d_in[ib + 3];
    const float* be1   = (const float*)d_in[ib + 4];
    const float* W2    = (const float*)d_in[ib + 5];
    const float* b2    = (const float*)d_in[ib + 6];
    const float* g2    = (const float*)d_in[ib + 7];
    const float* be2   = (const float*)d_in[ib + 8];
    const float* eps   = (const float*)d_in[ib + 9];
    const float* projW = (const float*)d_in[ib + 10];
    const float* projb = (const float*)d_in[ib + 11];

    int N = in_sizes[0] / 9;
    int E = in_sizes[1] / 2;
    int G = out_size / DOUT;
    int L = in_sizes[ib + 9];

    float *p_z, *p_t1, *p_pool;
    cudaGetSymbolAddress((void**)&p_z, g_z);
    cudaGetSymbolAddress((void**)&p_t1, g_t1);
    cudaGetSymbolAddress((void**)&p_pool, g_pool);

    cudaFuncSetAttribute(gemm_tc<H, false, true>,
                         cudaFuncAttributeMaxDynamicSharedMemorySize, SMEM_BYTES);
    cudaFuncSetAttribute(gemm_tc<H2, true, true>,
                         cudaFuncAttributeMaxDynamicSharedMemorySize, SMEM_BYTES);
    cudaFuncSetAttribute(gemm_tc<H, false, false>,
                         cudaFuncAttributeMaxDynamicSharedMemorySize, SMEM_BYTES);

    float invN = 1.f / (float)N;

    embed_kernel<<<N, H>>>(x, emb, N);
    zero_pool_kernel<<<cdiv((long long)G * H, 256), 256>>>(G);

    for (int l = 0; l < L; ++l) {
        init_z_kernel<<<cdiv((long long)N * 32, 256), 256>>>(N, eps, l);
        scatter_kernel<<<cdiv((long long)E * 32, 256), 256>>>(ei, E);

        zero_stats_kernel<<<1, 256>>>();
        gemm_tc<H, false, true><<<dim3(H2 / 128, cdiv(N, 128)), 256, SMEM_BYTES>>>(
            p_z, W1 + (size_t)l * H * H2, b1 + (size_t)l * H2, p_t1, N, H2);
        finalize_bn_kernel<<<1, 256>>>(g1 + (size_t)l * H2, be1 + (size_t)l * H2, H2, invN);

        zero_stats_kernel<<<1, 256>>>();
        gemm_tc<H2, true, true><<<dim3(H / 128, cdiv(N, 128)), 256, SMEM_BYTES>>>(
            p_t1, W2 + (size_t)l * H2 * H, b2 + (size_t)l * H, p_z, N, H);
        finalize_bn_kernel<<<1, 128>>>(g2 + (size_t)l * H, be2 + (size_t)l * H, H, invN);

        if (l < L - 1)
            bnrelu_kernel<<<cdiv((long long)N * 32, 256), 256>>>(N);
    }

    pool_kernel<<<cdiv((long long)N * 32, 256), 256>>>(batch, N);

    gemm_tc<H, false, false><<<dim3(DOUT / 128, cdiv(G, 128)), 256, SMEM_BYTES>>>(
        p_pool, projW, projb, (float*)d_out, G, DOUT);
}

// round 6
// speedup vs baseline: 2.0337x; 1.8728x over previous
#include <cuda_runtime.h>
#include <cuda_bf16.h>
#include <cstdint>
#include <cstddef>

// ---------------------------------------------------------------------------
// MolGIN R6: bf16x3 tensor-core GEMMs (ldmatrix + m16n8k16), CSR gather
// aggregation (atomic-free), fused BN stats.
// ---------------------------------------------------------------------------

#define H      128
#define H2     256
#define NMAX   100000
#define EMAX   1600000
#define GMAX   4096
#define DOUT   768

__device__ float g_h   [NMAX * H];
__device__ float g_z   [NMAX * H];
__device__ float g_t1  [NMAX * H2];
__device__ float g_sum [H2];
__device__ float g_sq  [H2];
__device__ float g_scale[H2];
__device__ float g_shift[H2];
__device__ float g_pool[GMAX * H];

// CSR scratch
__device__ int g_rowptr[NMAX + 1];
__device__ int g_cursor[NMAX];
__device__ int g_srcidx[EMAX];
__device__ int g_bsums [4096];

__device__ __constant__ int c_off[9] = {0, 119, 129, 140, 152, 161, 166, 174, 176};

__device__ __forceinline__ void red_add_v4(float* p, float4 v) {
    asm volatile("red.global.add.v4.f32 [%0], {%1,%2,%3,%4};"
                 :: "l"(p), "f"(v.x), "f"(v.y), "f"(v.z), "f"(v.w) : "memory");
}

__device__ __forceinline__ void ldsm_x4(uint32_t& r0, uint32_t& r1,
                                        uint32_t& r2, uint32_t& r3,
                                        const void* p) {
    uint32_t a = (uint32_t)__cvta_generic_to_shared(p);
    asm volatile("ldmatrix.sync.aligned.m8n8.x4.shared.b16 {%0,%1,%2,%3}, [%4];"
                 : "=r"(r0), "=r"(r1), "=r"(r2), "=r"(r3) : "r"(a));
}

__device__ __forceinline__ void ldsm_x4t(uint32_t& r0, uint32_t& r1,
                                         uint32_t& r2, uint32_t& r3,
                                         const void* p) {
    uint32_t a = (uint32_t)__cvta_generic_to_shared(p);
    asm volatile("ldmatrix.sync.aligned.m8n8.x4.trans.shared.b16 {%0,%1,%2,%3}, [%4];"
                 : "=r"(r0), "=r"(r1), "=r"(r2), "=r"(r3) : "r"(a));
}

__device__ __forceinline__ void mma_bf16(float* d, const uint32_t* a,
                                         uint32_t b0, uint32_t b1) {
    asm volatile("mma.sync.aligned.m16n8k16.row.col.f32.bf16.bf16.f32 "
                 "{%0,%1,%2,%3}, {%4,%5,%6,%7}, {%8,%9}, {%0,%1,%2,%3};"
                 : "+f"(d[0]), "+f"(d[1]), "+f"(d[2]), "+f"(d[3])
                 : "r"(a[0]), "r"(a[1]), "r"(a[2]), "r"(a[3]), "r"(b0), "r"(b1));
}

__device__ __forceinline__ void split_bf16(float v, __nv_bfloat16& hi, __nv_bfloat16& lo) {
    hi = __float2bfloat16(v);
    lo = __float2bfloat16(v - __bfloat162float(hi));
}

// ---------------------------------------------------------------------------
// AtomEncoder
// ---------------------------------------------------------------------------
__global__ void embed_kernel(const int* __restrict__ x,
                             const float* __restrict__ emb, int N) {
    __shared__ int idx[9];
    int n = blockIdx.x;
    int t = threadIdx.x;
    if (t < 9) idx[t] = x[(size_t)n * 9 + t] + c_off[t];
    __syncthreads();
    float s = 0.f;
#pragma unroll
    for (int f = 0; f < 9; ++f) s += emb[(size_t)idx[f] * H + t];
    g_h[(size_t)n * H + t] = s;
}

// ---------------------------------------------------------------------------
// CSR build: rowptr[d+1] = deg(d); inclusive scan; fill src ids
// ---------------------------------------------------------------------------
__global__ void zero_rowptr_kernel(int N) {
    int i = blockIdx.x * blockDim.x + threadIdx.x;
    if (i <= N) g_rowptr[i] = 0;
}
__global__ void count_kernel(const int* __restrict__ ei, int E) {
    int e = blockIdx.x * blockDim.x + threadIdx.x;
    if (e < E) atomicAdd(&g_rowptr[ei[(size_t)E + e] + 1], 1);
}
// per-block inclusive scan of 1024 elems (256 threads x 4)
__global__ void scan_block_kernel(int M) {
    __shared__ int sdata[256];
    int t = threadIdx.x;
    int base = blockIdx.x * 1024 + t * 4;
    int v[4];
#pragma unroll
    for (int i = 0; i < 4; ++i)
        v[i] = (base + i < M) ? g_rowptr[base + i] : 0;
    v[1] += v[0]; v[2] += v[1]; v[3] += v[2];
    sdata[t] = v[3];
    __syncthreads();
    for (int off = 1; off < 256; off <<= 1) {
        int x = (t >= off) ? sdata[t - off] : 0;
        __syncthreads();
        sdata[t] += x;
        __syncthreads();
    }
    int excl = sdata[t] - v[3];
#pragma unroll
    for (int i = 0; i < 4; ++i)
        if (base + i < M) g_rowptr[base + i] = v[i] + excl;
    if (t == 255) g_bsums[blockIdx.x] = sdata[255];
}
__global__ void scan_sums_kernel(int nb) {
    if (threadIdx.x == 0) {
        int acc = 0;
        for (int i = 0; i < nb; ++i) { int t = g_bsums[i]; g_bsums[i] = acc; acc += t; }
    }
}
__global__ void scan_add_kernel(int M) {
    int i = blockIdx.x * blockDim.x + threadIdx.x;
    if (i < M) g_rowptr[i] += g_bsums[i >> 10];
}
__global__ void init_cursor_kernel(int N) {
    int i = blockIdx.x * blockDim.x + threadIdx.x;
    if (i < N) g_cursor[i] = g_rowptr[i];
}
__global__ void fill_csr_kernel(const int* __restrict__ ei, int E) {
    int e = blockIdx.x * blockDim.x + threadIdx.x;
    if (e < E) {
        int d = ei[(size_t)E + e];
        int p = atomicAdd(&g_cursor[d], 1);
        g_srcidx[p] = ei[e];
    }
}

// ---------------------------------------------------------------------------
// z[n] = (1+eps)*h[n] + sum_{src in N(n)} h[src]   (atomic-free gather)
// ---------------------------------------------------------------------------
__global__ void gather_kernel(int N, const float* __restrict__ eps, int l) {
    int n = blockIdx.x;
    int t = threadIdx.x;
    int beg = g_rowptr[n], end = g_rowptr[n + 1];
    float s0 = 0.f, s1 = 0.f;
    int e = beg;
    for (; e + 2 <= end; e += 2) {
        int i0 = g_srcidx[e], i1 = g_srcidx[e + 1];
        s0 += g_h[(size_t)i0 * H + t];
        s1 += g_h[(size_t)i1 * H + t];
    }
    if (e < end) s0 += g_h[(size_t)g_srcidx[e] * H + t];
    float se = 1.f + eps[l];
    g_z[(size_t)n * H + t] = se * g_h[(size_t)n * H + t] + (s0 + s1);
}

__global__ void zero_stats_kernel() {
    int i = blockIdx.x * blockDim.x + threadIdx.x;
    if (i < H2) { g_sum[i] = 0.f; g_sq[i] = 0.f; }
}
__global__ void zero_pool_kernel(int G) {
    int i = blockIdx.x * blockDim.x + threadIdx.x;
    if (i < G * H) g_pool[i] = 0.f;
}

// ---------------------------------------------------------------------------
// bf16x3 tensor-core GEMM: C[N,NCOLS] = f(A)[N,K] @ W[K,NCOLS] + bias.
// f = relu(scale*x+shift) if FUSE_IN. Optional per-column sum/sumsq stats.
// 128x128 tile, BK=32, 8 warps (4Mx2N), warp tile 32x64, m16n8k16 via ldmatrix.
// ---------------------------------------------------------------------------
#define AS_STRIDE 40
#define WS_STRIDE 136

template <int K, bool FUSE_IN, bool STATS>
__global__ void __launch_bounds__(256, 2)
gemm_tc(const float* __restrict__ A, const float* __restrict__ W,
        const float* __restrict__ bias, float* __restrict__ C,
        int N, int NCOLS) {
    __shared__ __nv_bfloat16 As[2][128][AS_STRIDE];  // [hi/lo][m][k]
    __shared__ __nv_bfloat16 Ws[2][32][WS_STRIDE];   // [hi/lo][k][n]
    __shared__ float sSum[128];
    __shared__ float sSq[128];

    int tid  = threadIdx.x;
    int lane = tid & 31;
    int warp = tid >> 5;
    int q = lane >> 2;
    int c = lane & 3;
    int wm0 = (warp >> 1) * 32;
    int wn0 = (warp & 1) * 64;
    int rowBase = blockIdx.y * 128;
    int colBase = blockIdx.x * 128;

    if (STATS && tid < 128) { sSum[tid] = 0.f; sSq[tid] = 0.f; }

    float acc[2][8][4];
#pragma unroll
    for (int mt = 0; mt < 2; ++mt)
#pragma unroll
        for (int nt = 0; nt < 8; ++nt)
#pragma unroll
            for (int r = 0; r < 4; ++r) acc[mt][nt][r] = 0.f;

    int am  = tid >> 3;        // A row 0..31 (+32*i)
    int akq = (tid & 7) * 4;   // A k quad
    int wkr = tid >> 5;        // W k row 0..7 (+8*i)
    int wn4 = (tid & 31) * 4;  // W n quad

    const int NS = K / 32;
    float4 aP[4];

    // ---- tile helpers ----
    auto loadA = [&](int s, float4* r) {
#pragma unroll
        for (int i = 0; i < 4; ++i) {
            int gm = rowBase + am + 32 * i;
            r[i] = make_float4(0.f, 0.f, 0.f, 0.f);
            if (gm < N)
                r[i] = *(const float4*)(A + (size_t)gm * K + s * 32 + akq);
        }
    };
    auto storeA = [&](int s, float4* r) {
#pragma unroll
        for (int i = 0; i < 4; ++i) {
            float4 v = r[i];
            if (FUSE_IN) {
                int kk = s * 32 + akq;
                v.x = fmaxf(v.x * g_scale[kk + 0] + g_shift[kk + 0], 0.f);
                v.y = fmaxf(v.y * g_scale[kk + 1] + g_shift[kk + 1], 0.f);
                v.z = fmaxf(v.z * g_scale[kk + 2] + g_shift[kk + 2], 0.f);
                v.w = fmaxf(v.w * g_scale[kk + 3] + g_shift[kk + 3], 0.f);
            }
            int m = am + 32 * i;
            __nv_bfloat16 h0, l0, h1, l1, h2, l2, h3, l3;
            split_bf16(v.x, h0, l0); split_bf16(v.y, h1, l1);
            split_bf16(v.z, h2, l2); split_bf16(v.w, h3, l3);
            __nv_bfloat162 a01; a01.x = h0; a01.y = h1;
            __nv_bfloat162 a23; a23.x = h2; a23.y = h3;
            __nv_bfloat162 b01; b01.x = l0; b01.y = l1;
            __nv_bfloat162 b23; b23.x = l2; b23.y = l3;
            *(__nv_bfloat162*)&As[0][m][akq]     = a01;
            *(__nv_bfloat162*)&As[0][m][akq + 2] = a23;
            *(__nv_bfloat162*)&As[1][m][akq]     = b01;
            *(__nv_bfloat162*)&As[1][m][akq + 2] = b23;
        }
    };
    auto loadStoreW = [&](int s) {
#pragma unroll
        for (int i = 0; i < 4; ++i) {
            int k = wkr + 8 * i;
            float4 wv = *(const float4*)(W + (size_t)(s * 32 + k) * NCOLS + colBase + wn4);
            __nv_bfloat16 h0, l0, h1, l1, h2, l2, h3, l3;
            split_bf16(wv.x, h0, l0); split_bf16(wv.y, h1, l1);
            split_bf16(wv.z, h2, l2); split_bf16(wv.w, h3, l3);
            __nv_bfloat162 a01; a01.x = h0; a01.y = h1;
            __nv_bfloat162 a23; a23.x = h2; a23.y = h3;
            __nv_bfloat162 b01; b01.x = l0; b01.y = l1;
            __nv_bfloat162 b23; b23.x = l2; b23.y = l3;
            *(__nv_bfloat162*)&Ws[0][k][wn4]     = a01;
            *(__nv_bfloat162*)&Ws[0][k][wn4 + 2] = a23;
            *(__nv_bfloat162*)&Ws[1][k][wn4]     = b01;
            *(__nv_bfloat162*)&Ws[1][k][wn4 + 2] = b23;
        }
    };

    // ---- pipelined mainloop ----
    loadA(0, aP);
    storeA(0, aP);
    loadStoreW(0);
    __syncthreads();

    int a_row_off = lane & 15;             // ldmatrix lane->row
    int a_col_off = (lane >> 4) << 3;      // ldmatrix lane->col (0/8)

    for (int s = 0; s < NS; ++s) {
        if (s + 1 < NS) loadA(s + 1, aP);

#pragma unroll
        for (int kk = 0; kk < 32; kk += 16) {
            uint32_t ah[2][4], al[2][4];
#pragma unroll
            for (int mt = 0; mt < 2; ++mt) {
                int r = wm0 + mt * 16 + a_row_off;
                int cc = kk + a_col_off;
                ldsm_x4(ah[mt][0], ah[mt][1], ah[mt][2], ah[mt][3], &As[0][r][cc]);
                ldsm_x4(al[mt][0], al[mt][1], al[mt][2], al[mt][3], &As[1][r][cc]);
            }
#pragma unroll
            for (int nt2 = 0; nt2 < 8; nt2 += 2) {
                int br = kk + a_row_off;
                int bn = wn0 + nt2 * 8 + a_col_off;
                uint32_t bh[4], bl[4];
                ldsm_x4t(bh[0], bh[1], bh[2], bh[3], &Ws[0][br][bn]);
                ldsm_x4t(bl[0], bl[1], bl[2], bl[3], &Ws[1][br][bn]);
#pragma unroll
                for (int j = 0; j < 2; ++j) {
#pragma unroll
                    for (int mt = 0; mt < 2; ++mt) {
                        float* d = acc[mt][nt2 + j];
                        mma_bf16(d, al[mt], bh[2 * j], bh[2 * j + 1]);  // lo*hi
                        mma_bf16(d, ah[mt], bl[2 * j], bl[2 * j + 1]);  // hi*lo
                        mma_bf16(d, ah[mt], bh[2 * j], bh[2 * j + 1]);  // hi*hi
                    }
                }
            }
        }
        __syncthreads();
        if (s + 1 < NS) {
            storeA(s + 1, aP);
            loadStoreW(s + 1);
            __syncthreads();
        }
    }

    // ---- epilogue (c-frag layout: rows q/q+8, cols 2c/2c+1) ----
    float bc[8][2];
#pragma unroll
    for (int nt = 0; nt < 8; ++nt) {
        int col = colBase + wn0 + nt * 8 + 2 * c;
        bc[nt][0] = bias[col];
        bc[nt][1] = bias[col + 1];
    }

    float ps[8][2], pq[8][2];
    if (STATS) {
#pragma unroll
        for (int nt = 0; nt < 8; ++nt)
#pragma unroll
            for (int p = 0; p < 2; ++p) { ps[nt][p] = 0.f; pq[nt][p] = 0.f; }
    }

#pragma unroll
    for (int mt = 0; mt < 2; ++mt) {
        int r0 = rowBase + wm0 + mt * 16 + q;
        int r1 = r0 + 8;
        bool v0r = r0 < N, v1r = r1 < N;
#pragma unroll
        for (int nt = 0; nt < 8; ++nt) {
            int col = colBase + wn0 + nt * 8 + 2 * c;
            float v0 = acc[mt][nt][0] + bc[nt][0];
            float v1 = acc[mt][nt][1] + bc[nt][1];
            float v2 = acc[mt][nt][2] + bc[nt][0];
            float v3 = acc[mt][nt][3] + bc[nt][1];
            if (v0r) {
                *(float2*)(C + (size_t)r0 * NCOLS + col) = make_float2(v0, v1);
                if (STATS) {
                    ps[nt][0] += v0; pq[nt][0] += v0 * v0;
                    ps[nt][1] += v1; pq[nt][1] += v1 * v1;
                }
            }
            if (v1r) {
                *(float2*)(C + (size_t)r1 * NCOLS + col) = make_float2(v2, v3);
                if (STATS) {
                    ps[nt][0] += v2; pq[nt][0] += v2 * v2;
                    ps[nt][1] += v3; pq[nt][1] += v3 * v3;
                }
            }
        }
    }

    if (STATS) {
#pragma unroll
        for (int nt = 0; nt < 8; ++nt)
#pragma unroll
            for (int p = 0; p < 2; ++p) {
                float s = ps[nt][p], sq = pq[nt][p];
#pragma unroll
                for (int m = 4; m < 32; m <<= 1) {
                    s  += __shfl_xor_sync(0xffffffffu, s,  m);
                    sq += __shfl_xor_sync(0xffffffffu, sq, m);
                }
                if (lane < 4) {
                    atomicAdd(&sSum[wn0 + nt * 8 + 2 * c + p], s);
                    atomicAdd(&sSq [wn0 + nt * 8 + 2 * c + p], sq);
                }
            }
        __syncthreads();
        if (tid < 128) {
            atomicAdd(&g_sum[colBase + tid], sSum[tid]);
            atomicAdd(&g_sq [colBase + tid], sSq [tid]);
        }
    }
}

__global__ void finalize_bn_kernel(const float* __restrict__ gamma,
                                   const float* __restrict__ beta,
                                   int C, float invN) {
    int c = blockIdx.x * blockDim.x + threadIdx.x;
    if (c >= C) return;
    float m = g_sum[c] * invN;
    float v = g_sq[c] * invN - m * m;
    float s = gamma[c] * rsqrtf(v + 1e-5f);
    g_scale[c] = s;
    g_shift[c] = beta[c] - m * s;
}

__global__ void bnrelu_kernel(int N) {
    int i = blockIdx.x * blockDim.x + threadIdx.x;
    if (i >= N * (H / 4)) return;
    int c = (i & 31) * 4;
    float4 v = ((const float4*)g_z)[i];
    v.x = fmaxf(v.x * g_scale[c + 0] + g_shift[c + 0], 0.f);
    v.y = fmaxf(v.y * g_scale[c + 1] + g_shift[c + 1], 0.f);
    v.z = fmaxf(v.z * g_scale[c + 2] + g_shift[c + 2], 0.f);
    v.w = fmaxf(v.w * g_scale[c + 3] + g_shift[c + 3], 0.f);
    ((float4*)g_h)[i] = v;
}

__global__ void pool_kernel(const int* __restrict__ batch, int N) {
    long long gid = (long long)blockIdx.x * blockDim.x + threadIdx.x;
    int n = (int)(gid >> 5);
    if (n >= N) return;
    int lane = (int)(gid & 31);
    int c = lane * 4;
    int g = batch[n];
    float4 v = *(const float4*)(g_z + (size_t)n * H + c);
    v.x = fmaxf(v.x * g_scale[c + 0] + g_shift[c + 0], 0.f);
    v.y = fmaxf(v.y * g_scale[c + 1] + g_shift[c + 1], 0.f);
    v.z = fmaxf(v.z * g_scale[c + 2] + g_shift[c + 2], 0.f);
    v.w = fmaxf(v.w * g_scale[c + 3] + g_shift[c + 3], 0.f);
    red_add_v4(g_pool + (size_t)g * H + c, v);
}

static inline int cdiv(long long a, long long b) { return (int)((a + b - 1) / b); }

extern "C" void kernel_launch(void* const* d_in, const int* in_sizes, int n_in,
                              void* d_out, int out_size) {
    const int* x     = (const int*)d_in[0];
    const int* ei    = (const int*)d_in[1];
    const int* batch = (const int*)d_in[2];

    int ib = 3;
    for (int i = 3; i < n_in; ++i)
        if (in_sizes[i] == 178 * H) { ib = i; break; }

    const float* emb   = (const float*)d_in[ib + 0];
    const float* W1    = (const float*)d_in[ib + 1];
    const float* b1    = (const float*)d_in[ib + 2];
    const float* g1    = (const float*)d_in[ib + 3];
    const float* be1   = (const float*)d_in[ib + 4];
    const float* W2    = (const float*)d_in[ib + 5];
    const float* b2    = (const float*)d_in[ib + 6];
    const float* g2    = (const float*)d_in[ib + 7];
    const float* be2   = (const float*)d_in[ib + 8];
    const float* eps   = (const float*)d_in[ib + 9];
    const float* projW = (const float*)d_in[ib + 10];
    const float* projb = (const float*)d_in[ib + 11];

    int N = in_sizes[0] / 9;
    int E = in_sizes[1] / 2;
    int G = out_size / DOUT;
    int L = in_sizes[ib + 9];

    float *p_z, *p_t1, *p_pool;
    cudaGetSymbolAddress((void**)&p_z, g_z);
    cudaGetSymbolAddress((void**)&p_t1, g_t1);
    cudaGetSymbolAddress((void**)&p_pool, g_pool);

    float invN = 1.f / (float)N;
    int M = N + 1;
    int nScanBlocks = cdiv(M, 1024);

    embed_kernel<<<N, H>>>(x, emb, N);
    zero_pool_kernel<<<cdiv((long long)G * H, 256), 256>>>(G);

    // ---- CSR build (once; graph is fixed per launch) ----
    zero_rowptr_kernel<<<cdiv(M, 256), 256>>>(N);
    count_kernel<<<cdiv(E, 256), 256>>>(ei, E);
    scan_block_kernel<<<nScanBlocks, 256>>>(M);
    scan_sums_kernel<<<1, 32>>>(nScanBlocks);
    scan_add_kernel<<<cdiv(M, 256), 256>>>(M);
    init_cursor_kernel<<<cdiv(N, 256), 256>>>(N);
    fill_csr_kernel<<<cdiv(E, 256), 256>>>(ei, E);

    for (int l = 0; l < L; ++l) {
        gather_kernel<<<N, H>>>(N, eps, l);

        zero_stats_kernel<<<1, 256>>>();
        gemm_tc<H, false, true><<<dim3(H2 / 128, cdiv(N, 128)), 256>>>(
            p_z, W1 + (size_t)l * H * H2, b1 + (size_t)l * H2, p_t1, N, H2);
        finalize_bn_kernel<<<1, 256>>>(g1 + (size_t)l * H2, be1 + (size_t)l * H2, H2, invN);

        zero_stats_kernel<<<1, 256>>>();
        gemm_tc<H2, true, true><<<dim3(H / 128, cdiv(N, 128)), 256>>>(
            p_t1, W2 + (size_t)l * H2 * H, b2 + (size_t)l * H, p_z, N, H);
        finalize_bn_kernel<<<1, 128>>>(g2 + (size_t)l * H, be2 + (size_t)l * H, H, invN);

        if (l < L - 1)
            bnrelu_kernel<<<cdiv((long long)N * 32, 256), 256>>>(N);
    }

    pool_kernel<<<cdiv((long long)N * 32, 256), 256>>>(batch, N);

    gemm_tc<H, false, false><<<dim3(DOUT / 128, cdiv(G, 128)), 256>>>(
        p_pool, projW, projb, (float*)d_out, G, DOUT);
}

// round 7
// speedup vs baseline: 2.2770x; 1.1196x over previous
#include <cuda_runtime.h>
#include <cuda_bf16.h>
#include <cstdint>
#include <cstddef>

// ---------------------------------------------------------------------------
// MolGIN R7: bf16x3 TC GEMMs (ldmatrix, W reg-prefetch), warp-per-node CSR
// gather with fused BN2+ReLU, finalize_bn self-zeroing stats.
// ---------------------------------------------------------------------------

#define H      128
#define H2     256
#define NMAX   100000
#define EMAX   1600000
#define GMAX   4096
#define DOUT   768

__device__ float g_h   [NMAX * H];    // embed output (layer 0 input)
__device__ float g_z   [NMAX * H];    // t2 (raw pre-BN2 activations)
__device__ float g_z2  [NMAX * H];    // aggregated z (GEMM1 input)
__device__ float g_t1  [NMAX * H2];   // hidden activations
__device__ float g_sum [H2];
__device__ float g_sq  [H2];
__device__ float g_scale1[H2];        // BN1 (used by GEMM2 A-load)
__device__ float g_shift1[H2];
__device__ float g_scale2[H];         // BN2 (used by gather / pool)
__device__ float g_shift2[H];
__device__ float g_pool[GMAX * H];

// CSR scratch
__device__ int g_rowptr[NMAX + 1];
__device__ int g_cursor[NMAX];
__device__ int g_srcidx[EMAX];
__device__ int g_bsums [4096];

__device__ __constant__ int c_off[9] = {0, 119, 129, 140, 152, 161, 166, 174, 176};

__device__ __forceinline__ void red_add_v4(float* p, float4 v) {
    asm volatile("red.global.add.v4.f32 [%0], {%1,%2,%3,%4};"
                 :: "l"(p), "f"(v.x), "f"(v.y), "f"(v.z), "f"(v.w) : "memory");
}

__device__ __forceinline__ void ldsm_x4(uint32_t& r0, uint32_t& r1,
                                        uint32_t& r2, uint32_t& r3,
                                        const void* p) {
    uint32_t a = (uint32_t)__cvta_generic_to_shared(p);
    asm volatile("ldmatrix.sync.aligned.m8n8.x4.shared.b16 {%0,%1,%2,%3}, [%4];"
                 : "=r"(r0), "=r"(r1), "=r"(r2), "=r"(r3) : "r"(a));
}

__device__ __forceinline__ void ldsm_x4t(uint32_t& r0, uint32_t& r1,
                                         uint32_t& r2, uint32_t& r3,
                                         const void* p) {
    uint32_t a = (uint32_t)__cvta_generic_to_shared(p);
    asm volatile("ldmatrix.sync.aligned.m8n8.x4.trans.shared.b16 {%0,%1,%2,%3}, [%4];"
                 : "=r"(r0), "=r"(r1), "=r"(r2), "=r"(r3) : "r"(a));
}

__device__ __forceinline__ void mma_bf16(float* d, const uint32_t* a,
                                         uint32_t b0, uint32_t b1) {
    asm volatile("mma.sync.aligned.m16n8k16.row.col.f32.bf16.bf16.f32 "
                 "{%0,%1,%2,%3}, {%4,%5,%6,%7}, {%8,%9}, {%0,%1,%2,%3};"
                 : "+f"(d[0]), "+f"(d[1]), "+f"(d[2]), "+f"(d[3])
                 : "r"(a[0]), "r"(a[1]), "r"(a[2]), "r"(a[3]), "r"(b0), "r"(b1));
}

__device__ __forceinline__ void split_bf16(float v, __nv_bfloat16& hi, __nv_bfloat16& lo) {
    hi = __float2bfloat16(v);
    lo = __float2bfloat16(v - __bfloat162float(hi));
}

// ---------------------------------------------------------------------------
__global__ void embed_kernel(const int* __restrict__ x,
                             const float* __restrict__ emb, int N) {
    __shared__ int idx[9];
    int n = blockIdx.x;
    int t = threadIdx.x;
    if (t < 9) idx[t] = x[(size_t)n * 9 + t] + c_off[t];
    __syncthreads();
    float s = 0.f;
#pragma unroll
    for (int f = 0; f < 9; ++f) s += emb[(size_t)idx[f] * H + t];
    g_h[(size_t)n * H + t] = s;
}

// ---------------------------------------------------------------------------
// CSR build
// ---------------------------------------------------------------------------
__global__ void zero_rowptr_kernel(int N) {
    int i = blockIdx.x * blockDim.x + threadIdx.x;
    if (i <= N) g_rowptr[i] = 0;
}
__global__ void count_kernel(const int* __restrict__ ei, int E) {
    int e = blockIdx.x * blockDim.x + threadIdx.x;
    if (e < E) atomicAdd(&g_rowptr[ei[(size_t)E + e] + 1], 1);
}
__global__ void scan_block_kernel(int M) {
    __shared__ int sdata[256];
    int t = threadIdx.x;
    int base = blockIdx.x * 1024 + t * 4;
    int v[4];
#pragma unroll
    for (int i = 0; i < 4; ++i)
        v[i] = (base + i < M) ? g_rowptr[base + i] : 0;
    v[1] += v[0]; v[2] += v[1]; v[3] += v[2];
    sdata[t] = v[3];
    __syncthreads();
    for (int off = 1; off < 256; off <<= 1) {
        int x = (t >= off) ? sdata[t - off] : 0;
        __syncthreads();
        sdata[t] += x;
        __syncthreads();
    }
    int excl = sdata[t] - v[3];
#pragma unroll
    for (int i = 0; i < 4; ++i)
        if (base + i < M) g_rowptr[base + i] = v[i] + excl;
    if (t == 255) g_bsums[blockIdx.x] = sdata[255];
}
__global__ void scan_sums_kernel(int nb) {
    if (threadIdx.x == 0) {
        int acc = 0;
        for (int i = 0; i < nb; ++i) { int t = g_bsums[i]; g_bsums[i] = acc; acc += t; }
    }
}
__global__ void scan_add_kernel(int M) {
    int i = blockIdx.x * blockDim.x + threadIdx.x;
    if (i < M) g_rowptr[i] += g_bsums[i >> 10];
}
__global__ void init_cursor_kernel(int N) {
    int i = blockIdx.x * blockDim.x + threadIdx.x;
    if (i < N) g_cursor[i] = g_rowptr[i];
}
__global__ void fill_csr_kernel(const int* __restrict__ ei, int E) {
    int e = blockIdx.x * blockDim.x + threadIdx.x;
    if (e < E) {
        int d = ei[(size_t)E + e];
        int p = atomicAdd(&g_cursor[d], 1);
        g_srcidx[p] = ei[e];
    }
}

// ---------------------------------------------------------------------------
// Warp-per-node gather with optional fused BN2+ReLU on the source features:
//   z2[n] = (1+eps)*f(src[n]) + sum_{s in N(n)} f(src[s])
// BN=false: src = g_h (layer 0).  BN=true: src = g_z, f = relu(scale2*x+shift2).
// ---------------------------------------------------------------------------
template <bool BN>
__global__ void gather_kernel(int N, const float* __restrict__ eps, int l) {
    int gw = (blockIdx.x * blockDim.x + threadIdx.x) >> 5;
    if (gw >= N) return;
    int lane = threadIdx.x & 31;
    int c4 = lane * 4;
    const float* __restrict__ SRC = BN ? g_z : g_h;

    float4 sc = make_float4(0.f, 0.f, 0.f, 0.f), sh = sc;
    if (BN) {
        sc = *(const float4*)(g_scale2 + c4);
        sh = *(const float4*)(g_shift2 + c4);
    }

    auto f = [&](float4 v) -> float4 {
        if (BN) {
            v.x = fmaxf(v.x * sc.x + sh.x, 0.f);
            v.y = fmaxf(v.y * sc.y + sh.y, 0.f);
            v.z = fmaxf(v.z * sc.z + sh.z, 0.f);
            v.w = fmaxf(v.w * sc.w + sh.w, 0.f);
        }
        return v;
    };

    int beg = g_rowptr[gw], end = g_rowptr[gw + 1];
    float4 a0 = make_float4(0.f, 0.f, 0.f, 0.f);
    float4 a1 = a0;
    int e = beg;
    for (; e + 2 <= end; e += 2) {
        int s0 = g_srcidx[e], s1 = g_srcidx[e + 1];
        float4 v0 = f(*(const float4*)(SRC + (size_t)s0 * H + c4));
        float4 v1 = f(*(const float4*)(SRC + (size_t)s1 * H + c4));
        a0.x += v0.x; a0.y += v0.y; a0.z += v0.z; a0.w += v0.w;
        a1.x += v1.x; a1.y += v1.y; a1.z += v1.z; a1.w += v1.w;
    }
    if (e < end) {
        float4 v = f(*(const float4*)(SRC + (size_t)g_srcidx[e] * H + c4));
        a0.x += v.x; a0.y += v.y; a0.z += v.z; a0.w += v.w;
    }
    float se = 1.f + eps[l];
    float4 self = f(*(const float4*)(SRC + (size_t)gw * H + c4));
    float4 out;
    out.x = se * self.x + a0.x + a1.x;
    out.y = se * self.y + a0.y + a1.y;
    out.z = se * self.z + a0.z + a1.z;
    out.w = se * self.w + a0.w + a1.w;
    *(float4*)(g_z2 + (size_t)gw * H + c4) = out;
}

__global__ void zero_stats_kernel() {
    int i = blockIdx.x * blockDim.x + threadIdx.x;
    if (i < H2) { g_sum[i] = 0.f; g_sq[i] = 0.f; }
}
__global__ void zero_pool_kernel(int G) {
    int i = blockIdx.x * blockDim.x + threadIdx.x;
    if (i < G * H) g_pool[i] = 0.f;
}

// ---------------------------------------------------------------------------
// bf16x3 tensor-core GEMM (see R6). W gmem loads now reg-prefetched like A.
// ---------------------------------------------------------------------------
#define AS_STRIDE 40
#define WS_STRIDE 136

template <int K, bool FUSE_IN, bool STATS>
__global__ void __launch_bounds__(256, 2)
gemm_tc(const float* __restrict__ A, const float* __restrict__ W,
        const float* __restrict__ bias, float* __restrict__ C,
        int N, int NCOLS) {
    __shared__ __nv_bfloat16 As[2][128][AS_STRIDE];
    __shared__ __nv_bfloat16 Ws[2][32][WS_STRIDE];
    __shared__ float sSum[128];
    __shared__ float sSq[128];

    int tid  = threadIdx.x;
    int lane = tid & 31;
    int warp = tid >> 5;
    int q = lane >> 2;
    int c = lane & 3;
    int wm0 = (warp >> 1) * 32;
    int wn0 = (warp & 1) * 64;
    int rowBase = blockIdx.y * 128;
    int colBase = blockIdx.x * 128;

    if (STATS && tid < 128) { sSum[tid] = 0.f; sSq[tid] = 0.f; }

    float acc[2][8][4];
#pragma unroll
    for (int mt = 0; mt < 2; ++mt)
#pragma unroll
        for (int nt = 0; nt < 8; ++nt)
#pragma unroll
            for (int r = 0; r < 4; ++r) acc[mt][nt][r] = 0.f;

    int am  = tid >> 3;
    int akq = (tid & 7) * 4;
    int wkr = tid >> 5;
    int wn4 = (tid & 31) * 4;

    const int NS = K / 32;
    float4 aP[4], wP[4];

    auto loadA = [&](int s, float4* r) {
#pragma unroll
        for (int i = 0; i < 4; ++i) {
            int gm = rowBase + am + 32 * i;
            r[i] = make_float4(0.f, 0.f, 0.f, 0.f);
            if (gm < N)
                r[i] = *(const float4*)(A + (size_t)gm * K + s * 32 + akq);
        }
    };
    auto loadW = [&](int s, float4* r) {
#pragma unroll
        for (int i = 0; i < 4; ++i) {
            int k = wkr + 8 * i;
            r[i] = *(const float4*)(W + (size_t)(s * 32 + k) * NCOLS + colBase + wn4);
        }
    };
    auto storeA = [&](int s, float4* r) {
#pragma unroll
        for (int i = 0; i < 4; ++i) {
            float4 v = r[i];
            if (FUSE_IN) {
                int kk = s * 32 + akq;
                v.x = fmaxf(v.x * g_scale1[kk + 0] + g_shift1[kk + 0], 0.f);
                v.y = fmaxf(v.y * g_scale1[kk + 1] + g_shift1[kk + 1], 0.f);
                v.z = fmaxf(v.z * g_scale1[kk + 2] + g_shift1[kk + 2], 0.f);
                v.w = fmaxf(v.w * g_scale1[kk + 3] + g_shift1[kk + 3], 0.f);
            }
            int m = am + 32 * i;
            __nv_bfloat16 h0, l0, h1, l1, h2, l2, h3, l3;
            split_bf16(v.x, h0, l0); split_bf16(v.y, h1, l1);
            split_bf16(v.z, h2, l2); split_bf16(v.w, h3, l3);
            __nv_bfloat162 p01; p01.x = h0; p01.y = h1;
            __nv_bfloat162 p23; p23.x = h2; p23.y = h3;
            __nv_bfloat162 q01; q01.x = l0; q01.y = l1;
            __nv_bfloat162 q23; q23.x = l2; q23.y = l3;
            *(__nv_bfloat162*)&As[0][m][akq]     = p01;
            *(__nv_bfloat162*)&As[0][m][akq + 2] = p23;
            *(__nv_bfloat162*)&As[1][m][akq]     = q01;
            *(__nv_bfloat162*)&As[1][m][akq + 2] = q23;
        }
    };
    auto storeW = [&](float4* r) {
#pragma unroll
        for (int i = 0; i < 4; ++i) {
            float4 wv = r[i];
            int k = wkr + 8 * i;
            __nv_bfloat16 h0, l0, h1, l1, h2, l2, h3, l3;
            split_bf16(wv.x, h0, l0); split_bf16(wv.y, h1, l1);
            split_bf16(wv.z, h2, l2); split_bf16(wv.w, h3, l3);
            __nv_bfloat162 p01; p01.x = h0; p01.y = h1;
            __nv_bfloat162 p23; p23.x = h2; p23.y = h3;
            __nv_bfloat162 q01; q01.x = l0; q01.y = l1;
            __nv_bfloat162 q23; q23.x = l2; q23.y = l3;
            *(__nv_bfloat162*)&Ws[0][k][wn4]     = p01;
            *(__nv_bfloat162*)&Ws[0][k][wn4 + 2] = p23;
            *(__nv_bfloat162*)&Ws[1][k][wn4]     = q01;
            *(__nv_bfloat162*)&Ws[1][k][wn4 + 2] = q23;
        }
    };

    loadA(0, aP);
    loadW(0, wP);
    storeA(0, aP);
    storeW(wP);
    __syncthreads();

    int a_row_off = lane & 15;
    int a_col_off = (lane >> 4) << 3;

    for (int s = 0; s < NS; ++s) {
        if (s + 1 < NS) { loadA(s + 1, aP); loadW(s + 1, wP); }

#pragma unroll
        for (int kk = 0; kk < 32; kk += 16) {
            uint32_t ah[2][4], al[2][4];
#pragma unroll
            for (int mt = 0; mt < 2; ++mt) {
                int r = wm0 + mt * 16 + a_row_off;
                int cc = kk + a_col_off;
                ldsm_x4(ah[mt][0], ah[mt][1], ah[mt][2], ah[mt][3], &As[0][r][cc]);
                ldsm_x4(al[mt][0], al[mt][1], al[mt][2], al[mt][3], &As[1][r][cc]);
            }
#pragma unroll
            for (int nt2 = 0; nt2 < 8; nt2 += 2) {
                int br = kk + a_row_off;
                int bn = wn0 + nt2 * 8 + a_col_off;
                uint32_t bh[4], bl[4];
                ldsm_x4t(bh[0], bh[1], bh[2], bh[3], &Ws[0][br][bn]);
                ldsm_x4t(bl[0], bl[1], bl[2], bl[3], &Ws[1][br][bn]);
#pragma unroll
                for (int j = 0; j < 2; ++j) {
#pragma unroll
                    for (int mt = 0; mt < 2; ++mt) {
                        float* d = acc[mt][nt2 + j];
                        mma_bf16(d, al[mt], bh[2 * j], bh[2 * j + 1]);
                        mma_bf16(d, ah[mt], bl[2 * j], bl[2 * j + 1]);
                        mma_bf16(d, ah[mt], bh[2 * j], bh[2 * j + 1]);
                    }
                }
            }
        }
        __syncthreads();
        if (s + 1 < NS) {
            storeA(s + 1, aP);
            storeW(wP);
            __syncthreads();
        }
    }

    // ---- epilogue ----
    float bc[8][2];
#pragma unroll
    for (int nt = 0; nt < 8; ++nt) {
        int col = colBase + wn0 + nt * 8 + 2 * c;
        bc[nt][0] = bias[col];
        bc[nt][1] = bias[col + 1];
    }

    float ps[8][2], pq[8][2];
    if (STATS) {
#pragma unroll
        for (int nt = 0; nt < 8; ++nt)
#pragma unroll
            for (int p = 0; p < 2; ++p) { ps[nt][p] = 0.f; pq[nt][p] = 0.f; }
    }

#pragma unroll
    for (int mt = 0; mt < 2; ++mt) {
        int r0 = rowBase + wm0 + mt * 16 + q;
        int r1 = r0 + 8;
        bool v0r = r0 < N, v1r = r1 < N;
#pragma unroll
        for (int nt = 0; nt < 8; ++nt) {
            int col = colBase + wn0 + nt * 8 + 2 * c;
            float v0 = acc[mt][nt][0] + bc[nt][0];
            float v1 = acc[mt][nt][1] + bc[nt][1];
            float v2 = acc[mt][nt][2] + bc[nt][0];
            float v3 = acc[mt][nt][3] + bc[nt][1];
            if (v0r) {
                *(float2*)(C + (size_t)r0 * NCOLS + col) = make_float2(v0, v1);
                if (STATS) {
                    ps[nt][0] += v0; pq[nt][0] += v0 * v0;
                    ps[nt][1] += v1; pq[nt][1] += v1 * v1;
                }
            }
            if (v1r) {
                *(float2*)(C + (size_t)r1 * NCOLS + col) = make_float2(v2, v3);
                if (STATS) {
                    ps[nt][0] += v2; pq[nt][0] += v2 * v2;
                    ps[nt][1] += v3; pq[nt][1] += v3 * v3;
                }
            }
        }
    }

    if (STATS) {
#pragma unroll
        for (int nt = 0; nt < 8; ++nt)
#pragma unroll
            for (int p = 0; p < 2; ++p) {
                float s = ps[nt][p], sq = pq[nt][p];
#pragma unroll
                for (int m = 4; m < 32; m <<= 1) {
                    s  += __shfl_xor_sync(0xffffffffu, s,  m);
                    sq += __shfl_xor_sync(0xffffffffu, sq, m);
                }
                if (lane < 4) {
                    atomicAdd(&sSum[wn0 + nt * 8 + 2 * c + p], s);
                    atomicAdd(&sSq [wn0 + nt * 8 + 2 * c + p], sq);
                }
            }
        __syncthreads();
        if (tid < 128) {
            atomicAdd(&g_sum[colBase + tid], sSum[tid]);
            atomicAdd(&g_sq [colBase + tid], sSq [tid]);
        }
    }
}

// finalize BN scale/shift AND reset the stats accumulators for the next GEMM
__global__ void finalize_bn_kernel(const float* __restrict__ gamma,
                                   const float* __restrict__ beta,
                                   float* __restrict__ scale,
                                   float* __restrict__ shift,
                                   int C, float invN) {
    int c = blockIdx.x * blockDim.x + threadIdx.x;
    if (c >= C) return;
    float m = g_sum[c] * invN;
    float v = g_sq[c] * invN - m * m;
    float s = gamma[c] * rsqrtf(v + 1e-5f);
    scale[c] = s;
    shift[c] = beta[c] - m * s;
    g_sum[c] = 0.f;
    g_sq[c]  = 0.f;
}

__global__ void pool_kernel(const int* __restrict__ batch, int N) {
    long long gid = (long long)blockIdx.x * blockDim.x + threadIdx.x;
    int n = (int)(gid >> 5);
    if (n >= N) return;
    int lane = (int)(gid & 31);
    int c = lane * 4;
    int g = batch[n];
    float4 v = *(const float4*)(g_z + (size_t)n * H + c);
    v.x = fmaxf(v.x * g_scale2[c + 0] + g_shift2[c + 0], 0.f);
    v.y = fmaxf(v.y * g_scale2[c + 1] + g_shift2[c + 1], 0.f);
    v.z = fmaxf(v.z * g_scale2[c + 2] + g_shift2[c + 2], 0.f);
    v.w = fmaxf(v.w * g_scale2[c + 3] + g_shift2[c + 3], 0.f);
    red_add_v4(g_pool + (size_t)g * H + c, v);
}

static inline int cdiv(long long a, long long b) { return (int)((a + b - 1) / b); }

extern "C" void kernel_launch(void* const* d_in, const int* in_sizes, int n_in,
                              void* d_out, int out_size) {
    const int* x     = (const int*)d_in[0];
    const int* ei    = (const int*)d_in[1];
    const int* batch = (const int*)d_in[2];

    int ib = 3;
    for (int i = 3; i < n_in; ++i)
        if (in_sizes[i] == 178 * H) { ib = i; break; }

    const float* emb   = (const float*)d_in[ib + 0];
    const float* W1    = (const float*)d_in[ib + 1];
    const float* b1    = (const float*)d_in[ib + 2];
    const float* g1    = (const float*)d_in[ib + 3];
    const float* be1   = (const float*)d_in[ib + 4];
    const float* W2    = (const float*)d_in[ib + 5];
    const float* b2    = (const float*)d_in[ib + 6];
    const float* g2    = (const float*)d_in[ib + 7];
    const float* be2   = (const float*)d_in[ib + 8];
    const float* eps   = (const float*)d_in[ib + 9];
    const float* projW = (const float*)d_in[ib + 10];
    const float* projb = (const float*)d_in[ib + 11];

    int N = in_sizes[0] / 9;
    int E = in_sizes[1] / 2;
    int G = out_size / DOUT;
    int L = in_sizes[ib + 9];

    float *p_z, *p_z2, *p_t1, *p_pool, *p_s1, *p_h1, *p_s2, *p_h2;
    cudaGetSymbolAddress((void**)&p_z,   g_z);
    cudaGetSymbolAddress((void**)&p_z2,  g_z2);
    cudaGetSymbolAddress((void**)&p_t1,  g_t1);
    cudaGetSymbolAddress((void**)&p_pool, g_pool);
    cudaGetSymbolAddress((void**)&p_s1,  g_scale1);
    cudaGetSymbolAddress((void**)&p_h1,  g_shift1);
    cudaGetSymbolAddress((void**)&p_s2,  g_scale2);
    cudaGetSymbolAddress((void**)&p_h2,  g_shift2);

    float invN = 1.f / (float)N;
    int M = N + 1;
    int nScanBlocks = cdiv(M, 1024);

    embed_kernel<<<N, H>>>(x, emb, N);
    zero_pool_kernel<<<cdiv((long long)G * H, 256), 256>>>(G);
    zero_stats_kernel<<<1, 256>>>();

    // ---- CSR build ----
    zero_rowptr_kernel<<<cdiv(M, 256), 256>>>(N);
    count_kernel<<<cdiv(E, 256), 256>>>(ei, E);
    scan_block_kernel<<<nScanBlocks, 256>>>(M);
    scan_sums_kernel<<<1, 32>>>(nScanBlocks);
    scan_add_kernel<<<cdiv(M, 256), 256>>>(M);
    init_cursor_kernel<<<cdiv(N, 256), 256>>>(N);
    fill_csr_kernel<<<cdiv(E, 256), 256>>>(ei, E);

    for (int l = 0; l < L; ++l) {
        if (l == 0)
            gather_kernel<false><<<cdiv((long long)N * 32, 256), 256>>>(N, eps, l);
        else
            gather_kernel<true><<<cdiv((long long)N * 32, 256), 256>>>(N, eps, l);

        gemm_tc<H, false, true><<<dim3(H2 / 128, cdiv(N, 128)), 256>>>(
            p_z2, W1 + (size_t)l * H * H2, b1 + (size_t)l * H2, p_t1, N, H2);
        finalize_bn_kernel<<<1, 256>>>(g1 + (size_t)l * H2, be1 + (size_t)l * H2,
                                       p_s1, p_h1, H2, invN);

        gemm_tc<H2, true, true><<<dim3(H / 128, cdiv(N, 128)), 256>>>(
            p_t1, W2 + (size_t)l * H2 * H, b2 + (size_t)l * H, p_z, N, H);
        finalize_bn_kernel<<<1, 128>>>(g2 + (size_t)l * H, be2 + (size_t)l * H,
                                       p_s2, p_h2, H, invN);
    }

    pool_kernel<<<cdiv((long long)N * 32, 256), 256>>>(batch, N);

    gemm_tc<H, false, false><<<dim3(DOUT / 128, cdiv(G, 128)), 256>>>(
        p_pool, projW, projb, (float*)d_out, G, DOUT);
}

// round 8
// speedup vs baseline: 2.3029x; 1.0114x over previous
#include <cuda_runtime.h>
#include <cuda_bf16.h>
#include <cstdint>
#include <cstddef>

// ---------------------------------------------------------------------------
// MolGIN R8: gather unrolled x4 (MLP), merged zero kernels, cursor folded
// into scan. bf16x3 TC GEMMs unchanged from R7.
// ---------------------------------------------------------------------------

#define H      128
#define H2     256
#define NMAX   100000
#define EMAX   1600000
#define GMAX   4096
#define DOUT   768

__device__ float g_h   [NMAX * H];
__device__ float g_z   [NMAX * H];
__device__ float g_z2  [NMAX * H];
__device__ float g_t1  [NMAX * H2];
__device__ float g_sum [H2];
__device__ float g_sq  [H2];
__device__ float g_scale1[H2];
__device__ float g_shift1[H2];
__device__ float g_scale2[H];
__device__ float g_shift2[H];
__device__ float g_pool[GMAX * H];

__device__ int g_rowptr[NMAX + 1];
__device__ int g_cursor[NMAX];
__device__ int g_srcidx[EMAX];
__device__ int g_bsums [4096];

__device__ __constant__ int c_off[9] = {0, 119, 129, 140, 152, 161, 166, 174, 176};

__device__ __forceinline__ void red_add_v4(float* p, float4 v) {
    asm volatile("red.global.add.v4.f32 [%0], {%1,%2,%3,%4};"
                 :: "l"(p), "f"(v.x), "f"(v.y), "f"(v.z), "f"(v.w) : "memory");
}

__device__ __forceinline__ void ldsm_x4(uint32_t& r0, uint32_t& r1,
                                        uint32_t& r2, uint32_t& r3,
                                        const void* p) {
    uint32_t a = (uint32_t)__cvta_generic_to_shared(p);
    asm volatile("ldmatrix.sync.aligned.m8n8.x4.shared.b16 {%0,%1,%2,%3}, [%4];"
                 : "=r"(r0), "=r"(r1), "=r"(r2), "=r"(r3) : "r"(a));
}

__device__ __forceinline__ void ldsm_x4t(uint32_t& r0, uint32_t& r1,
                                         uint32_t& r2, uint32_t& r3,
                                         const void* p) {
    uint32_t a = (uint32_t)__cvta_generic_to_shared(p);
    asm volatile("ldmatrix.sync.aligned.m8n8.x4.trans.shared.b16 {%0,%1,%2,%3}, [%4];"
                 : "=r"(r0), "=r"(r1), "=r"(r2), "=r"(r3) : "r"(a));
}

__device__ __forceinline__ void mma_bf16(float* d, const uint32_t* a,
                                         uint32_t b0, uint32_t b1) {
    asm volatile("mma.sync.aligned.m16n8k16.row.col.f32.bf16.bf16.f32 "
                 "{%0,%1,%2,%3}, {%4,%5,%6,%7}, {%8,%9}, {%0,%1,%2,%3};"
                 : "+f"(d[0]), "+f"(d[1]), "+f"(d[2]), "+f"(d[3])
                 : "r"(a[0]), "r"(a[1]), "r"(a[2]), "r"(a[3]), "r"(b0), "r"(b1));
}

__device__ __forceinline__ void split_bf16(float v, __nv_bfloat16& hi, __nv_bfloat16& lo) {
    hi = __float2bfloat16(v);
    lo = __float2bfloat16(v - __bfloat162float(hi));
}

// ---------------------------------------------------------------------------
__global__ void embed_kernel(const int* __restrict__ x,
                             const float* __restrict__ emb, int N) {
    __shared__ int idx[9];
    int n = blockIdx.x;
    int t = threadIdx.x;
    if (t < 9) idx[t] = x[(size_t)n * 9 + t] + c_off[t];
    __syncthreads();
    float s = 0.f;
#pragma unroll
    for (int f = 0; f < 9; ++f) s += emb[(size_t)idx[f] * H + t];
    g_h[(size_t)n * H + t] = s;
}

// merged zeroing: rowptr, pool, stats
__global__ void zero_all_kernel(int N, int G) {
    int i = blockIdx.x * blockDim.x + threadIdx.x;
    if (i <= N) g_rowptr[i] = 0;
    if (i < G * H) g_pool[i] = 0.f;
    if (i < H2) { g_sum[i] = 0.f; g_sq[i] = 0.f; }
}

__global__ void count_kernel(const int* __restrict__ ei, int E) {
    int e = blockIdx.x * blockDim.x + threadIdx.x;
    if (e < E) atomicAdd(&g_rowptr[ei[(size_t)E + e] + 1], 1);
}
__global__ void scan_block_kernel(int M) {
    __shared__ int sdata[256];
    int t = threadIdx.x;
    int base = blockIdx.x * 1024 + t * 4;
    int v[4];
#pragma unroll
    for (int i = 0; i < 4; ++i)
        v[i] = (base + i < M) ? g_rowptr[base + i] : 0;
    v[1] += v[0]; v[2] += v[1]; v[3] += v[2];
    sdata[t] = v[3];
    __syncthreads();
    for (int off = 1; off < 256; off <<= 1) {
        int x = (t >= off) ? sdata[t - off] : 0;
        __syncthreads();
        sdata[t] += x;
        __syncthreads();
    }
    int excl = sdata[t] - v[3];
#pragma unroll
    for (int i = 0; i < 4; ++i)
        if (base + i < M) g_rowptr[base + i] = v[i] + excl;
    if (t == 255) g_bsums[blockIdx.x] = sdata[255];
}
__global__ void scan_sums_kernel(int nb) {
    if (threadIdx.x == 0) {
        int acc = 0;
        for (int i = 0; i < nb; ++i) { int t = g_bsums[i]; g_bsums[i] = acc; acc += t; }
    }
}
// add block offsets; also initialize cursor = final rowptr
__global__ void scan_add_kernel(int M, int N) {
    int i = blockIdx.x * blockDim.x + threadIdx.x;
    if (i < M) {
        int v = g_rowptr[i] + g_bsums[i >> 10];
        g_rowptr[i] = v;
        if (i < N) g_cursor[i] = v;
    }
}
__global__ void fill_csr_kernel(const int* __restrict__ ei, int E) {
    int e = blockIdx.x * blockDim.x + threadIdx.x;
    if (e < E) {
        int d = ei[(size_t)E + e];
        int p = atomicAdd(&g_cursor[d], 1);
        g_srcidx[p] = ei[e];
    }
}

// ---------------------------------------------------------------------------
// Warp-per-node gather, edge loop unrolled x4 for MLP.
//   z2[n] = (1+eps)*f(src[n]) + sum_{s in N(n)} f(src[s])
// BN=false: src = g_h (layer 0).  BN=true: src = g_z, f = relu(scale2*x+shift2).
// ---------------------------------------------------------------------------
template <bool BN>
__global__ void gather_kernel(int N, const float* __restrict__ eps, int l) {
    int gw = (blockIdx.x * blockDim.x + threadIdx.x) >> 5;
    if (gw >= N) return;
    int lane = threadIdx.x & 31;
    int c4 = lane * 4;
    const float* __restrict__ SRC = BN ? g_z : g_h;

    float4 sc = make_float4(0.f, 0.f, 0.f, 0.f), sh = sc;
    if (BN) {
        sc = *(const float4*)(g_scale2 + c4);
        sh = *(const float4*)(g_shift2 + c4);
    }
    auto f = [&](float4 v) -> float4 {
        if (BN) {
            v.x = fmaxf(v.x * sc.x + sh.x, 0.f);
            v.y = fmaxf(v.y * sc.y + sh.y, 0.f);
            v.z = fmaxf(v.z * sc.z + sh.z, 0.f);
            v.w = fmaxf(v.w * sc.w + sh.w, 0.f);
        }
        return v;
    };
    auto acc4 = [](float4& a, float4 v) {
        a.x += v.x; a.y += v.y; a.z += v.z; a.w += v.w;
    };

    int beg = g_rowptr[gw], end = g_rowptr[gw + 1];
    float4 a0 = make_float4(0.f, 0.f, 0.f, 0.f);
    float4 a1 = a0, a2 = a0, a3 = a0;
    int e = beg;
    for (; e + 4 <= end; e += 4) {
        int s0 = g_srcidx[e    ];
        int s1 = g_srcidx[e + 1];
        int s2 = g_srcidx[e + 2];
        int s3 = g_srcidx[e + 3];
        float4 v0 = *(const float4*)(SRC + (size_t)s0 * H + c4);
        float4 v1 = *(const float4*)(SRC + (size_t)s1 * H + c4);
        float4 v2 = *(const float4*)(SRC + (size_t)s2 * H + c4);
        float4 v3 = *(const float4*)(SRC + (size_t)s3 * H + c4);
        acc4(a0, f(v0)); acc4(a1, f(v1)); acc4(a2, f(v2)); acc4(a3, f(v3));
    }
    for (; e < end; ++e) {
        float4 v = *(const float4*)(SRC + (size_t)g_srcidx[e] * H + c4);
        acc4(a0, f(v));
    }
    float se = 1.f + eps[l];
    float4 self = f(*(const float4*)(SRC + (size_t)gw * H + c4));
    float4 out;
    out.x = se * self.x + (a0.x + a1.x) + (a2.x + a3.x);
    out.y = se * self.y + (a0.y + a1.y) + (a2.y + a3.y);
    out.z = se * self.z + (a0.z + a1.z) + (a2.z + a3.z);
    out.w = se * self.w + (a0.w + a1.w) + (a2.w + a3.w);
    *(float4*)(g_z2 + (size_t)gw * H + c4) = out;
}

// ---------------------------------------------------------------------------
// bf16x3 tensor-core GEMM (unchanged from R7)
// ---------------------------------------------------------------------------
#define AS_STRIDE 40
#define WS_STRIDE 136

template <int K, bool FUSE_IN, bool STATS>
__global__ void __launch_bounds__(256, 2)
gemm_tc(const float* __restrict__ A, const float* __restrict__ W,
        const float* __restrict__ bias, float* __restrict__ C,
        int N, int NCOLS) {
    __shared__ __nv_bfloat16 As[2][128][AS_STRIDE];
    __shared__ __nv_bfloat16 Ws[2][32][WS_STRIDE];
    __shared__ float sSum[128];
    __shared__ float sSq[128];

    int tid  = threadIdx.x;
    int lane = tid & 31;
    int warp = tid >> 5;
    int q = lane >> 2;
    int c = lane & 3;
    int wm0 = (warp >> 1) * 32;
    int wn0 = (warp & 1) * 64;
    int rowBase = blockIdx.y * 128;
    int colBase = blockIdx.x * 128;

    if (STATS && tid < 128) { sSum[tid] = 0.f; sSq[tid] = 0.f; }

    float acc[2][8][4];
#pragma unroll
    for (int mt = 0; mt < 2; ++mt)
#pragma unroll
        for (int nt = 0; nt < 8; ++nt)
#pragma unroll
            for (int r = 0; r < 4; ++r) acc[mt][nt][r] = 0.f;

    int am  = tid >> 3;
    int akq = (tid & 7) * 4;
    int wkr = tid >> 5;
    int wn4 = (tid & 31) * 4;

    const int NS = K / 32;
    float4 aP[4], wP[4];

    auto loadA = [&](int s, float4* r) {
#pragma unroll
        for (int i = 0; i < 4; ++i) {
            int gm = rowBase + am + 32 * i;
            r[i] = make_float4(0.f, 0.f, 0.f, 0.f);
            if (gm < N)
                r[i] = *(const float4*)(A + (size_t)gm * K + s * 32 + akq);
        }
    };
    auto loadW = [&](int s, float4* r) {
#pragma unroll
        for (int i = 0; i < 4; ++i) {
            int k = wkr + 8 * i;
            r[i] = *(const float4*)(W + (size_t)(s * 32 + k) * NCOLS + colBase + wn4);
        }
    };
    auto storeA = [&](int s, float4* r) {
#pragma unroll
        for (int i = 0; i < 4; ++i) {
            float4 v = r[i];
            if (FUSE_IN) {
                int kk = s * 32 + akq;
                v.x = fmaxf(v.x * g_scale1[kk + 0] + g_shift1[kk + 0], 0.f);
                v.y = fmaxf(v.y * g_scale1[kk + 1] + g_shift1[kk + 1], 0.f);
                v.z = fmaxf(v.z * g_scale1[kk + 2] + g_shift1[kk + 2], 0.f);
                v.w = fmaxf(v.w * g_scale1[kk + 3] + g_shift1[kk + 3], 0.f);
            }
            int m = am + 32 * i;
            __nv_bfloat16 h0, l0, h1, l1, h2, l2, h3, l3;
            split_bf16(v.x, h0, l0); split_bf16(v.y, h1, l1);
            split_bf16(v.z, h2, l2); split_bf16(v.w, h3, l3);
            __nv_bfloat162 p01; p01.x = h0; p01.y = h1;
            __nv_bfloat162 p23; p23.x = h2; p23.y = h3;
            __nv_bfloat162 q01; q01.x = l0; q01.y = l1;
            __nv_bfloat162 q23; q23.x = l2; q23.y = l3;
            *(__nv_bfloat162*)&As[0][m][akq]     = p01;
            *(__nv_bfloat162*)&As[0][m][akq + 2] = p23;
            *(__nv_bfloat162*)&As[1][m][akq]     = q01;
            *(__nv_bfloat162*)&As[1][m][akq + 2] = q23;
        }
    };
    auto storeW = [&](float4* r) {
#pragma unroll
        for (int i = 0; i < 4; ++i) {
            float4 wv = r[i];
            int k = wkr + 8 * i;
            __nv_bfloat16 h0, l0, h1, l1, h2, l2, h3, l3;
            split_bf16(wv.x, h0, l0); split_bf16(wv.y, h1, l1);
            split_bf16(wv.z, h2, l2); split_bf16(wv.w, h3, l3);
            __nv_bfloat162 p01; p01.x = h0; p01.y = h1;
            __nv_bfloat162 p23; p23.x = h2; p23.y = h3;
            __nv_bfloat162 q01; q01.x = l0; q01.y = l1;
            __nv_bfloat162 q23; q23.x = l2; q23.y = l3;
            *(__nv_bfloat162*)&Ws[0][k][wn4]     = p01;
            *(__nv_bfloat162*)&Ws[0][k][wn4 + 2] = p23;
            *(__nv_bfloat162*)&Ws[1][k][wn4]     = q01;
            *(__nv_bfloat162*)&Ws[1][k][wn4 + 2] = q23;
        }
    };

    loadA(0, aP);
    loadW(0, wP);
    storeA(0, aP);
    storeW(wP);
    __syncthreads();

    int a_row_off = lane & 15;
    int a_col_off = (lane >> 4) << 3;

    for (int s = 0; s < NS; ++s) {
        if (s + 1 < NS) { loadA(s + 1, aP); loadW(s + 1, wP); }

#pragma unroll
        for (int kk = 0; kk < 32; kk += 16) {
            uint32_t ah[2][4], al[2][4];
#pragma unroll
            for (int mt = 0; mt < 2; ++mt) {
                int r = wm0 + mt * 16 + a_row_off;
                int cc = kk + a_col_off;
                ldsm_x4(ah[mt][0], ah[mt][1], ah[mt][2], ah[mt][3], &As[0][r][cc]);
                ldsm_x4(al[mt][0], al[mt][1], al[mt][2], al[mt][3], &As[1][r][cc]);
            }
#pragma unroll
            for (int nt2 = 0; nt2 < 8; nt2 += 2) {
                int br = kk + a_row_off;
                int bn = wn0 + nt2 * 8 + a_col_off;
                uint32_t bh[4], bl[4];
                ldsm_x4t(bh[0], bh[1], bh[2], bh[3], &Ws[0][br][bn]);
                ldsm_x4t(bl[0], bl[1], bl[2], bl[3], &Ws[1][br][bn]);
#pragma unroll
                for (int j = 0; j < 2; ++j) {
#pragma unroll
                    for (int mt = 0; mt < 2; ++mt) {
                        float* d = acc[mt][nt2 + j];
                        mma_bf16(d, al[mt], bh[2 * j], bh[2 * j + 1]);
                        mma_bf16(d, ah[mt], bl[2 * j], bl[2 * j + 1]);
                        mma_bf16(d, ah[mt], bh[2 * j], bh[2 * j + 1]);
                    }
                }
            }
        }
        __syncthreads();
        if (s + 1 < NS) {
            storeA(s + 1, aP);
            storeW(wP);
            __syncthreads();
        }
    }

    float bc[8][2];
#pragma unroll
    for (int nt = 0; nt < 8; ++nt) {
        int col = colBase + wn0 + nt * 8 + 2 * c;
        bc[nt][0] = bias[col];
        bc[nt][1] = bias[col + 1];
    }

    float ps[8][2], pq[8][2];
    if (STATS) {
#pragma unroll
        for (int nt = 0; nt < 8; ++nt)
#pragma unroll
            for (int p = 0; p < 2; ++p) { ps[nt][p] = 0.f; pq[nt][p] = 0.f; }
    }

#pragma unroll
    for (int mt = 0; mt < 2; ++mt) {
        int r0 = rowBase + wm0 + mt * 16 + q;
        int r1 = r0 + 8;
        bool v0r = r0 < N, v1r = r1 < N;
#pragma unroll
        for (int nt = 0; nt < 8; ++nt) {
            int col = colBase + wn0 + nt * 8 + 2 * c;
            float v0 = acc[mt][nt][0] + bc[nt][0];
            float v1 = acc[mt][nt][1] + bc[nt][1];
            float v2 = acc[mt][nt][2] + bc[nt][0];
            float v3 = acc[mt][nt][3] + bc[nt][1];
            if (v0r) {
                *(float2*)(C + (size_t)r0 * NCOLS + col) = make_float2(v0, v1);
                if (STATS) {
                    ps[nt][0] += v0; pq[nt][0] += v0 * v0;
                    ps[nt][1] += v1; pq[nt][1] += v1 * v1;
                }
            }
            if (v1r) {
                *(float2*)(C + (size_t)r1 * NCOLS + col) = make_float2(v2, v3);
                if (STATS) {
                    ps[nt][0] += v2; pq[nt][0] += v2 * v2;
                    ps[nt][1] += v3; pq[nt][1] += v3 * v3;
                }
            }
        }
    }

    if (STATS) {
#pragma unroll
        for (int nt = 0; nt < 8; ++nt)
#pragma unroll
            for (int p = 0; p < 2; ++p) {
                float s = ps[nt][p], sq = pq[nt][p];
#pragma unroll
                for (int m = 4; m < 32; m <<= 1) {
                    s  += __shfl_xor_sync(0xffffffffu, s,  m);
                    sq += __shfl_xor_sync(0xffffffffu, sq, m);
                }
                if (lane < 4) {
                    atomicAdd(&sSum[wn0 + nt * 8 + 2 * c + p], s);
                    atomicAdd(&sSq [wn0 + nt * 8 + 2 * c + p], sq);
                }
            }
        __syncthreads();
        if (tid < 128) {
            atomicAdd(&g_sum[colBase + tid], sSum[tid]);
            atomicAdd(&g_sq [colBase + tid], sSq [tid]);
        }
    }
}

__global__ void finalize_bn_kernel(const float* __restrict__ gamma,
                                   const float* __restrict__ beta,
                                   float* __restrict__ scale,
                                   float* __restrict__ shift,
                                   int C, float invN) {
    int c = blockIdx.x * blockDim.x + threadIdx.x;
    if (c >= C) return;
    float m = g_sum[c] * invN;
    float v = g_sq[c] * invN - m * m;
    float s = gamma[c] * rsqrtf(v + 1e-5f);
    scale[c] = s;
    shift[c] = beta[c] - m * s;
    g_sum[c] = 0.f;
    g_sq[c]  = 0.f;
}

__global__ void pool_kernel(const int* __restrict__ batch, int N) {
    long long gid = (long long)blockIdx.x * blockDim.x + threadIdx.x;
    int n = (int)(gid >> 5);
    if (n >= N) return;
    int lane = (int)(gid & 31);
    int c = lane * 4;
    int g = batch[n];
    float4 v = *(const float4*)(g_z + (size_t)n * H + c);
    v.x = fmaxf(v.x * g_scale2[c + 0] + g_shift2[c + 0], 0.f);
    v.y = fmaxf(v.y * g_scale2[c + 1] + g_shift2[c + 1], 0.f);
    v.z = fmaxf(v.z * g_scale2[c + 2] + g_shift2[c + 2], 0.f);
    v.w = fmaxf(v.w * g_scale2[c + 3] + g_shift2[c + 3], 0.f);
    red_add_v4(g_pool + (size_t)g * H + c, v);
}

static inline int cdiv(long long a, long long b) { return (int)((a + b - 1) / b); }

extern "C" void kernel_launch(void* const* d_in, const int* in_sizes, int n_in,
                              void* d_out, int out_size) {
    const int* x     = (const int*)d_in[0];
    const int* ei    = (const int*)d_in[1];
    const int* batch = (const int*)d_in[2];

    int ib = 3;
    for (int i = 3; i < n_in; ++i)
        if (in_sizes[i] == 178 * H) { ib = i; break; }

    const float* emb   = (const float*)d_in[ib + 0];
    const float* W1    = (const float*)d_in[ib + 1];
    const float* b1    = (const float*)d_in[ib + 2];
    const float* g1    = (const float*)d_in[ib + 3];
    const float* be1   = (const float*)d_in[ib + 4];
    const float* W2    = (const float*)d_in[ib + 5];
    const float* b2    = (const float*)d_in[ib + 6];
    const float* g2    = (const float*)d_in[ib + 7];
    const float* be2   = (const float*)d_in[ib + 8];
    const float* eps   = (const float*)d_in[ib + 9];
    const float* projW = (const float*)d_in[ib + 10];
    const float* projb = (const float*)d_in[ib + 11];

    int N = in_sizes[0] / 9;
    int E = in_sizes[1] / 2;
    int G = out_size / DOUT;
    int L = in_sizes[ib + 9];

    float *p_z, *p_z2, *p_t1, *p_pool, *p_s1, *p_h1, *p_s2, *p_h2;
    cudaGetSymbolAddress((void**)&p_z,   g_z);
    cudaGetSymbolAddress((void**)&p_z2,  g_z2);
    cudaGetSymbolAddress((void**)&p_t1,  g_t1);
    cudaGetSymbolAddress((void**)&p_pool, g_pool);
    cudaGetSymbolAddress((void**)&p_s1,  g_scale1);
    cudaGetSymbolAddress((void**)&p_h1,  g_shift1);
    cudaGetSymbolAddress((void**)&p_s2,  g_scale2);
    cudaGetSymbolAddress((void**)&p_h2,  g_shift2);

    float invN = 1.f / (float)N;
    int M = N + 1;
    int nScanBlocks = cdiv(M, 1024);
    int zeroSpan = (G * H > M) ? G * H : M;

    embed_kernel<<<N, H>>>(x, emb, N);
    zero_all_kernel<<<cdiv(zeroSpan, 256), 256>>>(N, G);

    // ---- CSR build ----
    count_kernel<<<cdiv(E, 256), 256>>>(ei, E);
    scan_block_kernel<<<nScanBlocks, 256>>>(M);
    scan_sums_kernel<<<1, 32>>>(nScanBlocks);
    scan_add_kernel<<<cdiv(M, 256), 256>>>(M, N);
    fill_csr_kernel<<<cdiv(E, 256), 256>>>(ei, E);

    for (int l = 0; l < L; ++l) {
        if (l == 0)
            gather_kernel<false><<<cdiv((long long)N * 32, 256), 256>>>(N, eps, l);
        else
            gather_kernel<true><<<cdiv((long long)N * 32, 256), 256>>>(N, eps, l);

        gemm_tc<H, false, true><<<dim3(H2 / 128, cdiv(N, 128)), 256>>>(
            p_z2, W1 + (size_t)l * H * H2, b1 + (size_t)l * H2, p_t1, N, H2);
        finalize_bn_kernel<<<1, 256>>>(g1 + (size_t)l * H2, be1 + (size_t)l * H2,
                                       p_s1, p_h1, H2, invN);

        gemm_tc<H2, true, true><<<dim3(H / 128, cdiv(N, 128)), 256>>>(
            p_t1, W2 + (size_t)l * H2 * H, b2 + (size_t)l * H, p_z, N, H);
        finalize_bn_kernel<<<1, 128>>>(g2 + (size_t)l * H, be2 + (size_t)l * H,
                                       p_s2, p_h2, H, invN);
    }

    pool_kernel<<<cdiv((long long)N * 32, 256), 256>>>(batch, N);

    gemm_tc<H, false, false><<<dim3(DOUT / 128, cdiv(G, 128)), 256>>>(
        p_pool, projW, projb, (float*)d_out, G, DOUT);
}